// round 2
// baseline (speedup 1.0000x reference)
#include <cuda_runtime.h>
#include <cuda_fp16.h>
#include <cstdint>

#define DEVINL __device__ __forceinline__

// ---------------- problem constants ----------------
constexpr int B_   = 65536;
constexpr int DIN  = 256;
constexpr int H_   = 512;
constexpr int KTOT = DIN + H_;     // 768
constexpr int NTOT = 4 * H_;       // 2048 packed gate columns
constexpr int BM   = 128;
constexpr int BN   = 128;
constexpr int BKH  = 64;           // k-slice in halves (128 bytes/row)
constexpr int NIT  = KTOT / BKH;   // 12
constexpr int GN   = NTOT / BN;    // 16
constexpr int GM   = B_ / BM;      // 512
constexpr int NTH  = 256;
constexpr long long BH = (long long)B_ * H_;

// smem: [buf0 A 16K][buf0 B 16K][buf1 A 16K][buf1 B 16K]
constexpr uint32_t SMEM_BYTES = 65536;

// ---------------- device scratch ----------------
__device__ __half g_Wth[NTOT * KTOT];  // [n'][k] half, K contiguous
__device__ float  g_bias[NTOT];

// ---------------- helpers ----------------
DEVINL uint32_t smem_u32(const void* p) {
    uint32_t a;
    asm("{ .reg .u64 t; cvta.to.shared.u64 t, %1; cvt.u32.u64 %0, t; }" : "=r"(a) : "l"(p));
    return a;
}
DEVINL float tanh_fast(float x) { float y; asm("tanh.approx.f32 %0, %1;" : "=f"(y) : "f"(x)); return y; }
DEVINL float sig_fast(float x)  { return fmaf(tanh_fast(0.5f * x), 0.5f, 0.5f); }

DEVINL void ldsm4(uint32_t* r, uint32_t addr) {
    asm volatile("ldmatrix.sync.aligned.m8n8.x4.shared.b16 {%0,%1,%2,%3}, [%4];"
                 : "=r"(r[0]), "=r"(r[1]), "=r"(r[2]), "=r"(r[3]) : "r"(addr));
}
DEVINL void mma16816(float* d, const uint32_t* a, const uint32_t* b) {
    asm volatile("mma.sync.aligned.m16n8k16.row.col.f32.f16.f16.f32 "
                 "{%0,%1,%2,%3}, {%4,%5,%6,%7}, {%8,%9}, {%0,%1,%2,%3};"
                 : "+f"(d[0]), "+f"(d[1]), "+f"(d[2]), "+f"(d[3])
                 : "r"(a[0]), "r"(a[1]), "r"(a[2]), "r"(a[3]), "r"(b[0]), "r"(b[1]));
}
DEVINL void cpasync16(uint32_t dst, const void* src) {
    asm volatile("cp.async.cg.shared.global [%0], [%1], 16;" :: "r"(dst), "l"(src) : "memory");
}
DEVINL void sts64(uint32_t addr, uint32_t a, uint32_t b) {
    asm volatile("st.shared.v2.b32 [%0], {%1,%2};" :: "r"(addr), "r"(a), "r"(b) : "memory");
}
DEVINL uint32_t h2u(__half2 h) { return *reinterpret_cast<uint32_t*>(&h); }

// packed column index -> (h, g)
// n' = (h>>4)*64 + (g>>1)*32 + (h&15)*2 + (g&1)
DEVINL void unpack_np(int np, int& h, int& g) {
    int grp = np >> 6, wi = np & 63, pb = wi >> 5, id = wi & 31;
    h = (grp << 4) | (id >> 1);
    g = (pb << 1) | (id & 1);
}

// ---------------- weight/bias pack ----------------
__global__ void lstm_pack_kernel(const float* __restrict__ U, const float* __restrict__ bU,
                                 const float* __restrict__ W, const float* __restrict__ bW) {
    int idx = blockIdx.x * 256 + threadIdx.x;
    if (idx < NTOT * KTOT) {
        int np = idx / KTOT;
        int k  = idx - np * KTOT;
        int h, g; unpack_np(np, h, g);
        float v = (k < DIN) ? U[(g * DIN + k) * H_ + h]
                            : W[(g * H_ + (k - DIN)) * H_ + h];
        g_Wth[idx] = __float2half_rn(v);
    }
    if (idx < NTOT) {
        int h, g; unpack_np(idx, h, g);
        g_bias[idx] = bU[g * H_ + h] + bW[g * H_ + h];
    }
}

// ---------------- main fused kernel ----------------
__global__ void __launch_bounds__(NTH)
lstm_mma_kernel(const float* __restrict__ X, const float* __restrict__ Hold,
                const float* __restrict__ Cold, float* __restrict__ out) {
    extern __shared__ char smem[];
    const uint32_t sb = smem_u32(smem);
    const int tid = threadIdx.x;
    const int wid = tid >> 5, l = tid & 31;
    const int q = l & 3, s = l & 7;
    const int hi4 = l >> 4;          // 0/1: A ldmatrix k-half select
    const int hi3 = (l >> 3) & 1;    // 0/1: B ldmatrix k-half select

    const int m0 = (int)(blockIdx.x >> 4) * BM;   // n-fastest for A L2 reuse
    const int n0 = (int)(blockIdx.x & 15) * BN;
    const int wm = wid >> 1, wn = wid & 1;

    // ---- staging constants ----
    const int arow = tid >> 1;          // 0..127 (both A and B staging rows)
    const int akh0 = (tid & 1) * 32;    // starting half within 64-half row
    const int rsw  = arow & 7;
    const uint32_t a_sts_row = sb + (uint32_t)arow * 128u;
    const uint32_t b_sts_row = sb + 16384u + (uint32_t)arow * 128u;

    // ---- ldmatrix row-base addresses (buf offset added per iter) ----
    const uint32_t a_ld0 = sb + (uint32_t)((wm * 32 + (l & 15)) * 128);
    const uint32_t a_ld1 = a_ld0 + 16 * 128u;
    uint32_t b_ld[4];
    #pragma unroll
    for (int p = 0; p < 4; ++p)
        b_ld[p] = sb + 16384u + (uint32_t)((wn * 64 + p * 16 + hi4 * 8 + (l & 7)) * 128);

    // ---- accumulators ----
    float C0[8][4], C1[8][4];
    #pragma unroll
    for (int j = 0; j < 8; ++j)
        #pragma unroll
        for (int d = 0; d < 4; ++d) { C0[j][d] = 0.f; C1[j][d] = 0.f; }

    uint32_t sregs[16];  // prefetched A tile slice (32 halves)

    // ---- staging lambdas ----
    auto stageB = [&](int buf, int it) {
        const __half* src = g_Wth + (size_t)(n0 + arow) * KTOT + it * BKH + akh0;
        const uint32_t dbase = b_sts_row + (uint32_t)buf * 32768u;
        #pragma unroll
        for (int j = 0; j < 4; ++j) {
            int chunk = (akh0 >> 3) + j;
            cpasync16(dbase + (uint32_t)((chunk ^ rsw) << 4), src + j * 8);
        }
    };
    auto loadA = [&](int it) {
        const int kg = it * BKH;
        const float* aptr;
        if (kg < DIN) aptr = X    + (size_t)(m0 + arow) * DIN + kg + akh0;
        else          aptr = Hold + (size_t)(m0 + arow) * H_  + (kg - DIN) + akh0;
        #pragma unroll
        for (int i = 0; i < 8; ++i) {
            float4 v = __ldg((const float4*)(aptr + 4 * i));
            sregs[2 * i]     = h2u(__floats2half2_rn(v.x, v.y));
            sregs[2 * i + 1] = h2u(__floats2half2_rn(v.z, v.w));
        }
    };
    auto stsA = [&](int buf) {
        const uint32_t dbase = a_sts_row + (uint32_t)buf * 32768u;
        #pragma unroll
        for (int i = 0; i < 8; ++i) {
            int chunk = (akh0 >> 3) + (i >> 1);
            uint32_t off = (uint32_t)(((chunk ^ rsw) << 4) + (i & 1) * 8);
            sts64(dbase + off, sregs[2 * i], sregs[2 * i + 1]);
        }
    };
    auto compute = [&](int buf) {
        const uint32_t bofs = (uint32_t)buf * 32768u;
        #pragma unroll
        for (int kc = 0; kc < 4; ++kc) {
            uint32_t a0[4], a1[4];
            uint32_t aoff = (uint32_t)(((2 * kc + hi4) ^ s) << 4);
            ldsm4(a0, a_ld0 + bofs + aoff);
            ldsm4(a1, a_ld1 + bofs + aoff);
            uint32_t bfr[4][4];
            uint32_t boff = (uint32_t)(((2 * kc + hi3) ^ s) << 4);
            #pragma unroll
            for (int p = 0; p < 4; ++p) ldsm4(bfr[p], b_ld[p] + bofs + boff);
            #pragma unroll
            for (int nj = 0; nj < 8; ++nj) {
                const uint32_t* bb = &bfr[nj >> 1][(nj & 1) * 2];
                mma16816(C0[nj], a0, bb);
                mma16816(C1[nj], a1, bb);
            }
        }
    };

    // ---- prologue: stage iter 0 into buf0 ----
    stageB(0, 0);
    asm volatile("cp.async.commit_group;" ::: "memory");
    loadA(0);
    stsA(0);
    asm volatile("cp.async.wait_group 0;" ::: "memory");
    __syncthreads();

    // ---- main loop ----
    for (int it = 0; it < NIT; ++it) {
        const int buf = it & 1, nb = buf ^ 1;
        const bool pf = (it + 1) < NIT;
        if (pf) {
            stageB(nb, it + 1);
            asm volatile("cp.async.commit_group;" ::: "memory");
            loadA(it + 1);                  // LDG latency hidden by compute
        }
        compute(buf);
        if (pf) {
            stsA(nb);
            asm volatile("cp.async.wait_group 0;" ::: "memory");
        }
        __syncthreads();
    }

    // ---- epilogue: fuse gates ----
    const int nbase = n0 + wn * 64;
    const int h_base = nbase >> 2;         // 16 h per 64-col group
    float bi[4], bf_[4], bo[4], bc[4];
    #pragma unroll
    for (int j = 0; j < 4; ++j) {
        bi[j]  = g_bias[nbase + 8 * j + 2 * q];
        bf_[j] = g_bias[nbase + 8 * j + 2 * q + 1];
        bo[j]  = g_bias[nbase + 32 + 8 * j + 2 * q];
        bc[j]  = g_bias[nbase + 32 + 8 * j + 2 * q + 1];
    }

    #pragma unroll
    for (int mi = 0; mi < 2; ++mi) {
        const float (*Cm)[4] = (mi == 0) ? C0 : C1;
        #pragma unroll
        for (int rr = 0; rr < 2; ++rr) {
            const long long b = m0 + wm * 32 + mi * 16 + rr * 8 + (l >> 2);
            #pragma unroll
            for (int j = 0; j < 4; ++j) {
                float gi = Cm[j][2 * rr]         + bi[j];
                float gf = Cm[j][2 * rr + 1]     + bf_[j];
                float go = Cm[j + 4][2 * rr]     + bo[j];
                float gc = Cm[j + 4][2 * rr + 1] + bc[j];
                const int h = h_base + 4 * j + q;
                float co = __ldg(Cold + b * H_ + h);
                float i_ = sig_fast(gi);
                float f_ = sig_fast(gf);
                float o_ = sig_fast(go);
                float ct = tanh_fast(gc);
                float cn = fmaf(i_, ct, f_ * co);
                float hn = o_ * tanh_fast(cn);
                out[b * H_ + h]      = hn;
                out[BH + b * H_ + h] = cn;
            }
        }
    }
}

// ---------------- harness entry ----------------
extern "C" void kernel_launch(void* const* d_in, const int* in_sizes, int n_in,
                              void* d_out, int out_size) {
    const float* X    = (const float*)d_in[0];  // input_x [B, 256]
    const float* Hold = (const float*)d_in[1];  // h_old   [B, 512]
    const float* Cold = (const float*)d_in[2];  // c_old   [B, 512]
    const float* U    = (const float*)d_in[3];  // [4, 256, 512]
    const float* bU   = (const float*)d_in[4];  // [4, 512]
    const float* W    = (const float*)d_in[5];  // [4, 512, 512]
    const float* bW   = (const float*)d_in[6];  // [4, 512]
    float* out = (float*)d_out;                 // [h_new | c_new]
    (void)in_sizes; (void)n_in; (void)out_size;

    lstm_pack_kernel<<<(NTOT * KTOT + 255) / 256, 256>>>(U, bU, W, bW);

    cudaFuncSetAttribute(lstm_mma_kernel,
                         cudaFuncAttributeMaxDynamicSharedMemorySize, SMEM_BYTES);
    lstm_mma_kernel<<<GM * GN, NTH, SMEM_BYTES>>>(X, Hold, Cold, out);
}

// round 3
// speedup vs baseline: 1.1530x; 1.1530x over previous
#include <cuda_runtime.h>
#include <cuda_fp16.h>
#include <cstdint>

#define DEVINL __device__ __forceinline__

// ---------------- problem constants ----------------
constexpr int B_   = 65536;
constexpr int DIN  = 256;
constexpr int H_   = 512;
constexpr int KTOT = DIN + H_;     // 768
constexpr int NTOT = 4 * H_;       // 2048 packed gate columns
constexpr int BM   = 128;
constexpr int BN   = 256;
constexpr int BKH  = 64;           // k-slice in halves (128 B/row)
constexpr int NIT  = KTOT / BKH;   // 12
constexpr int GN   = NTOT / BN;    // 8
constexpr int GM   = B_ / BM;      // 512
constexpr int NTH  = 256;          // 8 warps: 2 (m) x 4 (n), warp tile 64x64
constexpr long long BH = (long long)B_ * H_;

// smem per stage: A 128x128B = 16K, B 256x128B = 32K
constexpr uint32_t STG_A = 16384;
constexpr uint32_t STG   = 49152;
constexpr uint32_t SMEM_BYTES = 3 * STG;   // 147456, 3-stage pipeline

// ---------------- device scratch ----------------
__device__ __half g_Ah[(size_t)B_ * KTOT];   // [b][k] packed [x|h] halves (96 MB)
__device__ __half g_Wth[NTOT * KTOT];        // [n'][k] halves, K contiguous
__device__ float  g_bias[NTOT];

// ---------------- helpers ----------------
DEVINL uint32_t smem_u32(const void* p) {
    uint32_t a;
    asm("{ .reg .u64 t; cvta.to.shared.u64 t, %1; cvt.u32.u64 %0, t; }" : "=r"(a) : "l"(p));
    return a;
}
DEVINL float tanh_fast(float x) { float y; asm("tanh.approx.f32 %0, %1;" : "=f"(y) : "f"(x)); return y; }
DEVINL float sig_fast(float x)  { return fmaf(tanh_fast(0.5f * x), 0.5f, 0.5f); }

DEVINL void ldsm4(uint32_t* r, uint32_t addr) {
    asm volatile("ldmatrix.sync.aligned.m8n8.x4.shared.b16 {%0,%1,%2,%3}, [%4];"
                 : "=r"(r[0]), "=r"(r[1]), "=r"(r[2]), "=r"(r[3]) : "r"(addr));
}
DEVINL void mma16816(float* d, const uint32_t* a, const uint32_t* b) {
    asm volatile("mma.sync.aligned.m16n8k16.row.col.f32.f16.f16.f32 "
                 "{%0,%1,%2,%3}, {%4,%5,%6,%7}, {%8,%9}, {%0,%1,%2,%3};"
                 : "+f"(d[0]), "+f"(d[1]), "+f"(d[2]), "+f"(d[3])
                 : "r"(a[0]), "r"(a[1]), "r"(a[2]), "r"(a[3]), "r"(b[0]), "r"(b[1]));
}
DEVINL void cpasync16(uint32_t dst, const void* src) {
    asm volatile("cp.async.cg.shared.global [%0], [%1], 16;" :: "r"(dst), "l"(src) : "memory");
}
#define CP_COMMIT() asm volatile("cp.async.commit_group;" ::: "memory")
DEVINL uint32_t h2u(__half2 h) { return *reinterpret_cast<uint32_t*>(&h); }

// packed column index -> (h, g):  n' = (h>>4)*64 + (g>>1)*32 + (h&15)*2 + (g&1)
DEVINL void unpack_np(int np, int& h, int& g) {
    int grp = np >> 6, wi = np & 63, pb = wi >> 5, id = wi & 31;
    h = (grp << 4) | (id >> 1);
    g = (pb << 1) | (id & 1);
}

// ---------------- pack kernels ----------------
__global__ void lstm_pack_w(const float* __restrict__ U, const float* __restrict__ bU,
                            const float* __restrict__ W, const float* __restrict__ bW) {
    int idx = blockIdx.x * 256 + threadIdx.x;
    if (idx < NTOT * KTOT) {
        int np = idx / KTOT;
        int k  = idx - np * KTOT;
        int h, g; unpack_np(np, h, g);
        float v = (k < DIN) ? U[(g * DIN + k) * H_ + h]
                            : W[(g * H_ + (k - DIN)) * H_ + h];
        g_Wth[idx] = __float2half_rn(v);
    }
    if (idx < NTOT) {
        int h, g; unpack_np(idx, h, g);
        g_bias[idx] = bU[g * H_ + h] + bW[g * H_ + h];
    }
}

// pack A = [x | h_old] -> half, 8 halves (16B) per thread
__global__ void lstm_pack_a(const float* __restrict__ X, const float* __restrict__ Hold) {
    int idx = blockIdx.x * 256 + threadIdx.x;         // one per 8-half chunk
    if (idx >= B_ * (KTOT / 8)) return;
    int b  = idx / (KTOT / 8);
    int k0 = (idx - b * (KTOT / 8)) * 8;
    const float* src = (k0 < DIN) ? (X + (size_t)b * DIN + k0)
                                  : (Hold + (size_t)b * H_ + (k0 - DIN));
    float4 v0 = __ldg((const float4*)src);
    float4 v1 = __ldg((const float4*)(src + 4));
    uint4 o;
    o.x = h2u(__floats2half2_rn(v0.x, v0.y));
    o.y = h2u(__floats2half2_rn(v0.z, v0.w));
    o.z = h2u(__floats2half2_rn(v1.x, v1.y));
    o.w = h2u(__floats2half2_rn(v1.z, v1.w));
    *(uint4*)(g_Ah + (size_t)b * KTOT + k0) = o;
}

// ---------------- main fused kernel ----------------
__global__ void __launch_bounds__(NTH)
lstm_mma_kernel(const float* __restrict__ Cold, float* __restrict__ out) {
    extern __shared__ char smem[];
    const uint32_t sb = smem_u32(smem);
    const int tid = threadIdx.x;
    const int wid = tid >> 5, l = tid & 31;
    const int q = l & 3, s = l & 7;
    const int hi4 = l >> 4;          // A/B k-half selects (same scheme as R2, verified)
    const int hi3 = (l >> 3) & 1;

    const int m0 = (int)(blockIdx.x >> 3) * BM;   // n-fastest for A L2 reuse
    const int n0 = (int)(blockIdx.x & 7) * BN;
    const int wm = wid >> 2, wn = wid & 3;        // 2 x 4 warps, each 64(m) x 64(n)

    // ---- ldmatrix row-base addresses (stage offset + k-chunk added per use) ----
    uint32_t a_ld[4], b_ld[4];
    #pragma unroll
    for (int mf = 0; mf < 4; ++mf)
        a_ld[mf] = sb + (uint32_t)((wm * 64 + mf * 16 + (l & 15)) * 128);
    #pragma unroll
    for (int p = 0; p < 4; ++p)
        b_ld[p] = sb + STG_A + (uint32_t)((wn * 64 + p * 16 + hi4 * 8 + (l & 7)) * 128);

    // ---- staging constants ----
    const int ar  = tid >> 1;            // A row 0..127, 2 threads/row
    const int ac0 = (tid & 1) * 4;       // first 16B chunk of 8
    const uint32_t a_dst = sb + (uint32_t)ar * 128u;
    const uint32_t b_dst = sb + STG_A + (uint32_t)tid * 128u;   // B row = tid
    const __half* a_srcb = g_Ah  + (size_t)(m0 + ar)  * KTOT + ac0 * 8;
    const __half* b_srcb = g_Wth + (size_t)(n0 + tid) * KTOT;

    auto stage = [&](int st, int it) {
        const uint32_t so = (uint32_t)st * STG;
        const __half* as = a_srcb + it * BKH;
        #pragma unroll
        for (int j = 0; j < 4; ++j) {
            int c = ac0 + j;
            cpasync16(a_dst + so + (uint32_t)((c ^ (ar & 7)) << 4), as + j * 8);
        }
        const __half* bs = b_srcb + it * BKH;
        #pragma unroll
        for (int j = 0; j < 8; ++j)
            cpasync16(b_dst + so + (uint32_t)((j ^ (tid & 7)) << 4), bs + j * 8);
        CP_COMMIT();
    };

    // ---- accumulators ----
    float C[4][8][4];
    #pragma unroll
    for (int mf = 0; mf < 4; ++mf)
        #pragma unroll
        for (int nj = 0; nj < 8; ++nj)
            #pragma unroll
            for (int d = 0; d < 4; ++d) C[mf][nj][d] = 0.f;

    auto compute = [&](int st) {
        const uint32_t so = (uint32_t)st * STG;
        #pragma unroll
        for (int kc = 0; kc < 4; ++kc) {
            uint32_t afr[4][4], bfr[4][4];
            const uint32_t aoff = so + (uint32_t)(((2 * kc + hi4) ^ s) << 4);
            const uint32_t boff = so + (uint32_t)(((2 * kc + hi3) ^ s) << 4);
            #pragma unroll
            for (int mf = 0; mf < 4; ++mf) ldsm4(afr[mf], a_ld[mf] + aoff);
            #pragma unroll
            for (int p = 0; p < 4; ++p)    ldsm4(bfr[p], b_ld[p] + boff);
            #pragma unroll
            for (int mf = 0; mf < 4; ++mf)
                #pragma unroll
                for (int nj = 0; nj < 8; ++nj)
                    mma16816(C[mf][nj], afr[mf], &bfr[nj >> 1][(nj & 1) * 2]);
        }
    };

    // ---- 3-stage pipeline ----
    stage(0, 0);
    stage(1, 1);
    stage(2, 2);

    for (int it = 0; it < NIT; ++it) {
        if (it < NIT - 2)      asm volatile("cp.async.wait_group 2;" ::: "memory");
        else if (it < NIT - 1) asm volatile("cp.async.wait_group 1;" ::: "memory");
        else                   asm volatile("cp.async.wait_group 0;" ::: "memory");
        __syncthreads();
        compute(it % 3);
        __syncthreads();                       // all reads of buf it%3 done
        if (it + 3 < NIT) stage(it % 3, it + 3);
    }

    // ---- epilogue: fuse gates ----
    const int nbase  = n0 + wn * 64;
    const int h_base = nbase >> 2;             // 16 h per 64-col group
    float bi[4], bf_[4], bo[4], bc[4];
    #pragma unroll
    for (int j = 0; j < 4; ++j) {
        bi[j]  = __ldg(g_bias + nbase + 8 * j + 2 * q);
        bf_[j] = __ldg(g_bias + nbase + 8 * j + 2 * q + 1);
        bo[j]  = __ldg(g_bias + nbase + 32 + 8 * j + 2 * q);
        bc[j]  = __ldg(g_bias + nbase + 32 + 8 * j + 2 * q + 1);
    }

    #pragma unroll
    for (int mf = 0; mf < 4; ++mf) {
        #pragma unroll
        for (int rr = 0; rr < 2; ++rr) {
            const long long b = m0 + wm * 64 + mf * 16 + rr * 8 + (l >> 2);
            #pragma unroll
            for (int j = 0; j < 4; ++j) {
                float gi = C[mf][j][2 * rr]         + bi[j];
                float gf = C[mf][j][2 * rr + 1]     + bf_[j];
                float go = C[mf][j + 4][2 * rr]     + bo[j];
                float gc = C[mf][j + 4][2 * rr + 1] + bc[j];
                const int h = h_base + 4 * j + q;
                float co = __ldg(Cold + b * H_ + h);
                float i_ = sig_fast(gi);
                float f_ = sig_fast(gf);
                float o_ = sig_fast(go);
                float ct = tanh_fast(gc);
                float cn = fmaf(i_, ct, f_ * co);
                float hn = o_ * tanh_fast(cn);
                out[b * H_ + h]      = hn;
                out[BH + b * H_ + h] = cn;
            }
        }
    }
}

// ---------------- harness entry ----------------
extern "C" void kernel_launch(void* const* d_in, const int* in_sizes, int n_in,
                              void* d_out, int out_size) {
    const float* X    = (const float*)d_in[0];  // input_x [B, 256]
    const float* Hold = (const float*)d_in[1];  // h_old   [B, 512]
    const float* Cold = (const float*)d_in[2];  // c_old   [B, 512]
    const float* U    = (const float*)d_in[3];  // [4, 256, 512]
    const float* bU   = (const float*)d_in[4];  // [4, 512]
    const float* W    = (const float*)d_in[5];  // [4, 512, 512]
    const float* bW   = (const float*)d_in[6];  // [4, 512]
    float* out = (float*)d_out;                 // [h_new | c_new]
    (void)in_sizes; (void)n_in; (void)out_size;

    lstm_pack_w<<<(NTOT * KTOT + 255) / 256, 256>>>(U, bU, W, bW);
    lstm_pack_a<<<(B_ * (KTOT / 8) + 255) / 256, 256>>>(X, Hold);

    cudaFuncSetAttribute(lstm_mma_kernel,
                         cudaFuncAttributeMaxDynamicSharedMemorySize, SMEM_BYTES);
    lstm_mma_kernel<<<GM * GN, NTH, SMEM_BYTES>>>(Cold, out);
}

// round 4
// speedup vs baseline: 1.1864x; 1.0289x over previous
#include <cuda_runtime.h>
#include <cuda_fp16.h>
#include <cstdint>

#define DEVINL __device__ __forceinline__

// ---------------- problem constants ----------------
constexpr int B_   = 65536;
constexpr int DIN  = 256;
constexpr int H_   = 512;
constexpr int KTOT = DIN + H_;     // 768
constexpr int NTOT = 4 * H_;       // 2048 packed gate columns
constexpr int BM   = 128;
constexpr int BN   = 256;
constexpr int BKH  = 64;           // k-slice in halves (128 B/row)
constexpr int NIT  = KTOT / BKH;   // 12
constexpr int GN   = NTOT / BN;    // 8
constexpr int GM   = B_ / BM;      // 512
constexpr int NTH  = 256;          // 8 warps: 2 (m) x 4 (n), warp tile 64x64
constexpr long long BH = (long long)B_ * H_;

// smem per stage: A 128x128B = 16K, B 256x128B = 32K
constexpr uint32_t STG_A = 16384;
constexpr uint32_t STG   = 49152;
constexpr int      NSTG  = 4;
constexpr uint32_t SMEM_BYTES = NSTG * STG;   // 196608

// ---------------- device scratch ----------------
__device__ __half g_Ah[(size_t)B_ * KTOT];   // [b][k] packed [x|h] halves (96 MB)
__device__ __half g_Wth[NTOT * KTOT];        // [n'][k] halves, K contiguous
__device__ float  g_bias[NTOT];

// ---------------- helpers ----------------
DEVINL uint32_t smem_u32(const void* p) {
    uint32_t a;
    asm("{ .reg .u64 t; cvta.to.shared.u64 t, %1; cvt.u32.u64 %0, t; }" : "=r"(a) : "l"(p));
    return a;
}
DEVINL float tanh_fast(float x) { float y; asm("tanh.approx.f32 %0, %1;" : "=f"(y) : "f"(x)); return y; }
DEVINL float sig_fast(float x)  { return fmaf(tanh_fast(0.5f * x), 0.5f, 0.5f); }

DEVINL void ldsm4(uint32_t* r, uint32_t addr) {
    asm volatile("ldmatrix.sync.aligned.m8n8.x4.shared.b16 {%0,%1,%2,%3}, [%4];"
                 : "=r"(r[0]), "=r"(r[1]), "=r"(r[2]), "=r"(r[3]) : "r"(addr));
}
DEVINL void mma16816(float* d, const uint32_t* a, const uint32_t* b) {
    asm volatile("mma.sync.aligned.m16n8k16.row.col.f32.f16.f16.f32 "
                 "{%0,%1,%2,%3}, {%4,%5,%6,%7}, {%8,%9}, {%0,%1,%2,%3};"
                 : "+f"(d[0]), "+f"(d[1]), "+f"(d[2]), "+f"(d[3])
                 : "r"(a[0]), "r"(a[1]), "r"(a[2]), "r"(a[3]), "r"(b[0]), "r"(b[1]));
}
DEVINL void cpasync16(uint32_t dst, const void* src) {
    asm volatile("cp.async.cg.shared.global [%0], [%1], 16;" :: "r"(dst), "l"(src) : "memory");
}
#define CP_COMMIT() asm volatile("cp.async.commit_group;" ::: "memory")
DEVINL uint32_t h2u(__half2 h) { return *reinterpret_cast<uint32_t*>(&h); }

// packed column index -> (h, g):  n' = (h>>4)*64 + (g>>1)*32 + (h&15)*2 + (g&1)
DEVINL void unpack_np(int np, int& h, int& g) {
    int grp = np >> 6, wi = np & 63, pb = wi >> 5, id = wi & 31;
    h = (grp << 4) | (id >> 1);
    g = (pb << 1) | (id & 1);
}

// ---------------- pack kernels ----------------
__global__ void lstm_pack_w(const float* __restrict__ U, const float* __restrict__ bU,
                            const float* __restrict__ W, const float* __restrict__ bW) {
    int idx = blockIdx.x * 256 + threadIdx.x;
    if (idx < NTOT * KTOT) {
        int np = idx / KTOT;
        int k  = idx - np * KTOT;
        int h, g; unpack_np(np, h, g);
        float v = (k < DIN) ? U[(g * DIN + k) * H_ + h]
                            : W[(g * H_ + (k - DIN)) * H_ + h];
        g_Wth[idx] = __float2half_rn(v);
    }
    if (idx < NTOT) {
        int h, g; unpack_np(idx, h, g);
        g_bias[idx] = bU[g * H_ + h] + bW[g * H_ + h];
    }
}

// pack A = [x | h_old] -> half, 8 halves (16B) per thread
__global__ void lstm_pack_a(const float* __restrict__ X, const float* __restrict__ Hold) {
    int idx = blockIdx.x * 256 + threadIdx.x;
    if (idx >= B_ * (KTOT / 8)) return;
    int b  = idx / (KTOT / 8);
    int k0 = (idx - b * (KTOT / 8)) * 8;
    const float* src = (k0 < DIN) ? (X + (size_t)b * DIN + k0)
                                  : (Hold + (size_t)b * H_ + (k0 - DIN));
    float4 v0 = __ldg((const float4*)src);
    float4 v1 = __ldg((const float4*)(src + 4));
    uint4 o;
    o.x = h2u(__floats2half2_rn(v0.x, v0.y));
    o.y = h2u(__floats2half2_rn(v0.z, v0.w));
    o.z = h2u(__floats2half2_rn(v1.x, v1.y));
    o.w = h2u(__floats2half2_rn(v1.z, v1.w));
    *(uint4*)(g_Ah + (size_t)b * KTOT + k0) = o;
}

// ---------------- main fused kernel ----------------
__global__ void __launch_bounds__(NTH)
lstm_mma_kernel(const float* __restrict__ Cold, float* __restrict__ out) {
    extern __shared__ char smem[];
    const uint32_t sb = smem_u32(smem);
    const int tid = threadIdx.x;
    const int wid = tid >> 5, l = tid & 31;
    const int q = l & 3, s = l & 7;
    const int hi4 = l >> 4;
    const int hi3 = (l >> 3) & 1;

    const int m0 = (int)(blockIdx.x >> 3) * BM;   // n-fastest for A L2 reuse
    const int n0 = (int)(blockIdx.x & 7) * BN;
    const int wm = wid >> 2, wn = wid & 3;        // 2 x 4 warps, each 64(m) x 64(n)

    // ---- ldmatrix row-base addresses ----
    uint32_t a_ld[4], b_ld[4];
    #pragma unroll
    for (int mf = 0; mf < 4; ++mf)
        a_ld[mf] = sb + (uint32_t)((wm * 64 + mf * 16 + (l & 15)) * 128);
    #pragma unroll
    for (int p = 0; p < 4; ++p)
        b_ld[p] = sb + STG_A + (uint32_t)((wn * 64 + p * 16 + hi4 * 8 + (l & 7)) * 128);

    // ---- staging constants ----
    const int ar  = tid >> 1;            // A row 0..127, 2 threads/row
    const int ac0 = (tid & 1) * 4;       // first 16B chunk of 8
    const uint32_t a_dst = sb + (uint32_t)ar * 128u;
    const uint32_t b_dst = sb + STG_A + (uint32_t)tid * 128u;   // B row = tid
    const __half* a_srcb = g_Ah  + (size_t)(m0 + ar)  * KTOT + ac0 * 8;
    const __half* b_srcb = g_Wth + (size_t)(n0 + tid) * KTOT;

    auto stage = [&](int st, int it) {
        const uint32_t so = (uint32_t)st * STG;
        const __half* as = a_srcb + it * BKH;
        #pragma unroll
        for (int j = 0; j < 4; ++j) {
            int c = ac0 + j;
            cpasync16(a_dst + so + (uint32_t)((c ^ (ar & 7)) << 4), as + j * 8);
        }
        const __half* bs = b_srcb + it * BKH;
        #pragma unroll
        for (int j = 0; j < 8; ++j)
            cpasync16(b_dst + so + (uint32_t)((j ^ (tid & 7)) << 4), bs + j * 8);
        CP_COMMIT();
    };

    // ---- accumulators ----
    float C[4][8][4];
    #pragma unroll
    for (int mf = 0; mf < 4; ++mf)
        #pragma unroll
        for (int nj = 0; nj < 8; ++nj)
            #pragma unroll
            for (int d = 0; d < 4; ++d) C[mf][nj][d] = 0.f;

    auto compute = [&](int st) {
        const uint32_t so = (uint32_t)st * STG;
        #pragma unroll
        for (int kc = 0; kc < 4; ++kc) {
            uint32_t afr[4][4], bfr[4][4];
            const uint32_t aoff = so + (uint32_t)(((2 * kc + hi4) ^ s) << 4);
            const uint32_t boff = so + (uint32_t)(((2 * kc + hi3) ^ s) << 4);
            #pragma unroll
            for (int mf = 0; mf < 4; ++mf) ldsm4(afr[mf], a_ld[mf] + aoff);
            #pragma unroll
            for (int p = 0; p < 4; ++p)    ldsm4(bfr[p], b_ld[p] + boff);
            #pragma unroll
            for (int mf = 0; mf < 4; ++mf)
                #pragma unroll
                for (int nj = 0; nj < 8; ++nj)
                    mma16816(C[mf][nj], afr[mf], &bfr[nj >> 1][(nj & 1) * 2]);
        }
    };

    // ---- 4-stage pipeline, stage-before-compute, one barrier per iter ----
    stage(0, 0);
    stage(1, 1);
    stage(2, 2);

    for (int it = 0; it < NIT; ++it) {
        if (it < NIT - 2)      asm volatile("cp.async.wait_group 2;" ::: "memory");
        else if (it < NIT - 1) asm volatile("cp.async.wait_group 1;" ::: "memory");
        else                   asm volatile("cp.async.wait_group 0;" ::: "memory");
        __syncthreads();   // (a) tile `it` visible to all; (b) buf (it+3)%4 fully read
        if (it + 3 < NIT) stage((it + 3) % NSTG, it + 3);
        compute(it % NSTG);
    }

    // ---- epilogue: fuse gates ----
    const int nbase  = n0 + wn * 64;
    const int h_base = nbase >> 2;             // 16 h per 64-col group
    float bi[4], bf_[4], bo[4], bc[4];
    #pragma unroll
    for (int j = 0; j < 4; ++j) {
        bi[j]  = __ldg(g_bias + nbase + 8 * j + 2 * q);
        bf_[j] = __ldg(g_bias + nbase + 8 * j + 2 * q + 1);
        bo[j]  = __ldg(g_bias + nbase + 32 + 8 * j + 2 * q);
        bc[j]  = __ldg(g_bias + nbase + 32 + 8 * j + 2 * q + 1);
    }

    #pragma unroll
    for (int mf = 0; mf < 4; ++mf) {
        #pragma unroll
        for (int rr = 0; rr < 2; ++rr) {
            const long long b = m0 + wm * 64 + mf * 16 + rr * 8 + (l >> 2);
            #pragma unroll
            for (int j = 0; j < 4; ++j) {
                float gi = C[mf][j][2 * rr]         + bi[j];
                float gf = C[mf][j][2 * rr + 1]     + bf_[j];
                float go = C[mf][j + 4][2 * rr]     + bo[j];
                float gc = C[mf][j + 4][2 * rr + 1] + bc[j];
                const int h = h_base + 4 * j + q;
                float co = __ldg(Cold + b * H_ + h);
                float i_ = sig_fast(gi);
                float f_ = sig_fast(gf);
                float o_ = sig_fast(go);
                float ct = tanh_fast(gc);
                float cn = fmaf(i_, ct, f_ * co);
                float hn = o_ * tanh_fast(cn);
                out[b * H_ + h]      = hn;
                out[BH + b * H_ + h] = cn;
            }
        }
    }
}

// ---------------- harness entry ----------------
extern "C" void kernel_launch(void* const* d_in, const int* in_sizes, int n_in,
                              void* d_out, int out_size) {
    const float* X    = (const float*)d_in[0];  // input_x [B, 256]
    const float* Hold = (const float*)d_in[1];  // h_old   [B, 512]
    const float* Cold = (const float*)d_in[2];  // c_old   [B, 512]
    const float* U    = (const float*)d_in[3];  // [4, 256, 512]
    const float* bU   = (const float*)d_in[4];  // [4, 512]
    const float* W    = (const float*)d_in[5];  // [4, 512, 512]
    const float* bW   = (const float*)d_in[6];  // [4, 512]
    float* out = (float*)d_out;                 // [h_new | c_new]
    (void)in_sizes; (void)n_in; (void)out_size;

    lstm_pack_w<<<(NTOT * KTOT + 255) / 256, 256>>>(U, bU, W, bW);
    lstm_pack_a<<<(B_ * (KTOT / 8) + 255) / 256, 256>>>(X, Hold);

    cudaFuncSetAttribute(lstm_mma_kernel,
                         cudaFuncAttributeMaxDynamicSharedMemorySize, SMEM_BYTES);
    lstm_mma_kernel<<<GM * GN, NTH, SMEM_BYTES>>>(Cold, out);
}

// round 5
// speedup vs baseline: 1.1926x; 1.0053x over previous
#include <cuda_runtime.h>
#include <cuda_fp16.h>
#include <cstdint>

#define DEVINL __device__ __forceinline__

// ---------------- problem constants ----------------
constexpr int B_   = 65536;
constexpr int DIN  = 256;
constexpr int H_   = 512;
constexpr int KTOT = DIN + H_;     // 768
constexpr int NTOT = 4 * H_;       // 2048 packed gate columns
constexpr int BM   = 128;
constexpr int BN   = 256;
constexpr int BKH  = 64;           // k-slice in halves (128 B/row)
constexpr int NIT  = KTOT / BKH;   // 12
constexpr int GN   = NTOT / BN;    // 8
constexpr int GM   = B_ / BM;      // 512
constexpr int NTH  = 256;          // 8 warps: 2 (m) x 4 (n), warp tile 64x64
constexpr long long BH = (long long)B_ * H_;

// smem per stage: A 128x128B = 16K, B 256x128B = 32K
constexpr uint32_t STG_A = 16384;
constexpr uint32_t STG   = 49152;
constexpr int      NSTG  = 4;
constexpr uint32_t SMEM_BYTES = NSTG * STG;   // 196608
// gate buffer (epilogue) reuses bytes [0, 131072) = stages 0..2 (stage 3 still live)

// ---------------- device scratch ----------------
__device__ __half g_Ah[(size_t)B_ * KTOT];   // [b][k] packed [x|h] halves (96 MB)
__device__ __half g_Wth[NTOT * KTOT];        // [n'][k] halves, K contiguous
__device__ float  g_bias[NTOT];

// ---------------- helpers ----------------
DEVINL uint32_t smem_u32(const void* p) {
    uint32_t a;
    asm("{ .reg .u64 t; cvta.to.shared.u64 t, %1; cvt.u32.u64 %0, t; }" : "=r"(a) : "l"(p));
    return a;
}
DEVINL float tanh_fast(float x) { float y; asm("tanh.approx.f32 %0, %1;" : "=f"(y) : "f"(x)); return y; }
DEVINL float sig_fast(float x)  { return fmaf(tanh_fast(0.5f * x), 0.5f, 0.5f); }

DEVINL void ldsm4(uint32_t* r, uint32_t addr) {
    asm volatile("ldmatrix.sync.aligned.m8n8.x4.shared.b16 {%0,%1,%2,%3}, [%4];"
                 : "=r"(r[0]), "=r"(r[1]), "=r"(r[2]), "=r"(r[3]) : "r"(addr));
}
DEVINL void mma16816(float* d, const uint32_t* a, const uint32_t* b) {
    asm volatile("mma.sync.aligned.m16n8k16.row.col.f32.f16.f16.f32 "
                 "{%0,%1,%2,%3}, {%4,%5,%6,%7}, {%8,%9}, {%0,%1,%2,%3};"
                 : "+f"(d[0]), "+f"(d[1]), "+f"(d[2]), "+f"(d[3])
                 : "r"(a[0]), "r"(a[1]), "r"(a[2]), "r"(a[3]), "r"(b[0]), "r"(b[1]));
}
DEVINL void cpasync16(uint32_t dst, const void* src) {
    asm volatile("cp.async.cg.shared.global [%0], [%1], 16;" :: "r"(dst), "l"(src) : "memory");
}
#define CP_COMMIT() asm volatile("cp.async.commit_group;" ::: "memory")
DEVINL uint32_t h2u(__half2 h) { return *reinterpret_cast<uint32_t*>(&h); }
DEVINL void sts_v2f(uint32_t addr, float a, float b) {
    asm volatile("st.shared.v2.f32 [%0], {%1,%2};" :: "r"(addr), "f"(a), "f"(b) : "memory");
}
DEVINL float4 lds_v4f(uint32_t addr) {
    float4 v;
    asm volatile("ld.shared.v4.f32 {%0,%1,%2,%3}, [%4];"
                 : "=f"(v.x), "=f"(v.y), "=f"(v.z), "=f"(v.w) : "r"(addr));
    return v;
}

// packed column index -> (h, g):  n' = (h>>2)*16 + g*4 + (h&3)
DEVINL void unpack_np(int np, int& h, int& g) {
    int Q = np >> 4, wi = np & 15;
    g = wi >> 2;
    h = (Q << 2) | (wi & 3);
}

// gate-smem swizzled address for (row 0..127, col c 0..255), fp32 elements.
// 16B unit u = c>>2; (q, j) = (u>>2, u&3); phys unit = (4q + (j ^ (q&3) ^ ((q>>2)&3))) ^ (row&7)
DEVINL uint32_t gaddr(int row, int c) {
    int u = c >> 2;
    int q = u >> 2, j = u & 3;
    int us = (4 * q + (j ^ (q & 3) ^ ((q >> 2) & 3))) ^ (row & 7);
    return (uint32_t)(row * 1024 + us * 16 + (c & 3) * 4);
}

// ---------------- pack kernels ----------------
__global__ void lstm_pack_w(const float* __restrict__ U, const float* __restrict__ bU,
                            const float* __restrict__ W, const float* __restrict__ bW) {
    int idx = blockIdx.x * 256 + threadIdx.x;
    if (idx < NTOT * KTOT) {
        int np = idx / KTOT;
        int k  = idx - np * KTOT;
        int h, g; unpack_np(np, h, g);
        float v = (k < DIN) ? U[(g * DIN + k) * H_ + h]
                            : W[(g * H_ + (k - DIN)) * H_ + h];
        g_Wth[idx] = __float2half_rn(v);
    }
    if (idx < NTOT) {
        int h, g; unpack_np(idx, h, g);
        g_bias[idx] = bU[g * H_ + h] + bW[g * H_ + h];
    }
}

// pack A = [x | h_old] -> half, 8 halves (16B) per thread
__global__ void lstm_pack_a(const float* __restrict__ X, const float* __restrict__ Hold) {
    int idx = blockIdx.x * 256 + threadIdx.x;
    if (idx >= B_ * (KTOT / 8)) return;
    int b  = idx / (KTOT / 8);
    int k0 = (idx - b * (KTOT / 8)) * 8;
    const float* src = (k0 < DIN) ? (X + (size_t)b * DIN + k0)
                                  : (Hold + (size_t)b * H_ + (k0 - DIN));
    float4 v0 = __ldg((const float4*)src);
    float4 v1 = __ldg((const float4*)(src + 4));
    uint4 o;
    o.x = h2u(__floats2half2_rn(v0.x, v0.y));
    o.y = h2u(__floats2half2_rn(v0.z, v0.w));
    o.z = h2u(__floats2half2_rn(v1.x, v1.y));
    o.w = h2u(__floats2half2_rn(v1.z, v1.w));
    *(uint4*)(g_Ah + (size_t)b * KTOT + k0) = o;
}

// ---------------- main fused kernel ----------------
__global__ void __launch_bounds__(NTH)
lstm_mma_kernel(const float* __restrict__ Cold, float* __restrict__ out) {
    extern __shared__ char smem[];
    const uint32_t sb = smem_u32(smem);
    const int tid = threadIdx.x;
    const int wid = tid >> 5, l = tid & 31;
    const int s = l & 7;
    const int hi4 = l >> 4;
    const int hi3 = (l >> 3) & 1;

    const int m0 = (int)(blockIdx.x >> 3) * BM;   // n-fastest for A L2 reuse
    const int n0 = (int)(blockIdx.x & 7) * BN;
    const int wm = wid >> 2, wn = wid & 3;        // 2 x 4 warps, each 64(m) x 64(n)

    // ---- ldmatrix row-base addresses ----
    uint32_t a_ld[4], b_ld[4];
    #pragma unroll
    for (int mf = 0; mf < 4; ++mf)
        a_ld[mf] = sb + (uint32_t)((wm * 64 + mf * 16 + (l & 15)) * 128);
    #pragma unroll
    for (int p = 0; p < 4; ++p)
        b_ld[p] = sb + STG_A + (uint32_t)((wn * 64 + p * 16 + hi4 * 8 + (l & 7)) * 128);

    // ---- staging constants ----
    const int ar  = tid >> 1;            // A row 0..127, 2 threads/row
    const int ac0 = (tid & 1) * 4;       // first 16B chunk of 8
    const uint32_t a_dst = sb + (uint32_t)ar * 128u;
    const uint32_t b_dst = sb + STG_A + (uint32_t)tid * 128u;   // B row = tid
    const __half* a_srcb = g_Ah  + (size_t)(m0 + ar)  * KTOT + ac0 * 8;
    const __half* b_srcb = g_Wth + (size_t)(n0 + tid) * KTOT;

    auto stage = [&](int st, int it) {
        const uint32_t so = (uint32_t)st * STG;
        const __half* as = a_srcb + it * BKH;
        #pragma unroll
        for (int j = 0; j < 4; ++j) {
            int c = ac0 + j;
            cpasync16(a_dst + so + (uint32_t)((c ^ (ar & 7)) << 4), as + j * 8);
        }
        const __half* bs = b_srcb + it * BKH;
        #pragma unroll
        for (int j = 0; j < 8; ++j)
            cpasync16(b_dst + so + (uint32_t)((j ^ (tid & 7)) << 4), bs + j * 8);
        CP_COMMIT();
    };

    // ---- accumulators ----
    float C[4][8][4];
    #pragma unroll
    for (int mf = 0; mf < 4; ++mf)
        #pragma unroll
        for (int nj = 0; nj < 8; ++nj)
            #pragma unroll
            for (int d = 0; d < 4; ++d) C[mf][nj][d] = 0.f;

    auto compute = [&](int st) {
        const uint32_t so = (uint32_t)st * STG;
        #pragma unroll
        for (int kc = 0; kc < 4; ++kc) {
            uint32_t afr[4][4], bfr[4][4];
            const uint32_t aoff = so + (uint32_t)(((2 * kc + hi4) ^ s) << 4);
            const uint32_t boff = so + (uint32_t)(((2 * kc + hi3) ^ s) << 4);
            #pragma unroll
            for (int mf = 0; mf < 4; ++mf) ldsm4(afr[mf], a_ld[mf] + aoff);
            #pragma unroll
            for (int p = 0; p < 4; ++p)    ldsm4(bfr[p], b_ld[p] + boff);
            #pragma unroll
            for (int mf = 0; mf < 4; ++mf)
                #pragma unroll
                for (int nj = 0; nj < 8; ++nj)
                    mma16816(C[mf][nj], afr[mf], &bfr[nj >> 1][(nj & 1) * 2]);
        }
    };

    // ---- 4-stage pipeline, stage-before-compute, one barrier per iter ----
    stage(0, 0);
    stage(1, 1);
    stage(2, 2);

    for (int it = 0; it < NIT; ++it) {
        if (it < NIT - 2)      asm volatile("cp.async.wait_group 2;" ::: "memory");
        else if (it < NIT - 1) asm volatile("cp.async.wait_group 1;" ::: "memory");
        else                   asm volatile("cp.async.wait_group 0;" ::: "memory");
        __syncthreads();   // (a) tile `it` visible; (b) buf (it+3)%4 fully read
        if (it + 3 < NIT) stage((it + 3) % NSTG, it + 3);
        compute(it % NSTG);
    }

    // ---- epilogue pass 1: frags -> gate smem (bytes [0,128K) = stages 0..2) ----
    // safe without a barrier: last compute reads stage 3 (>= 147456) only.
    {
        const int q = l & 3;
        #pragma unroll
        for (int mf = 0; mf < 4; ++mf) {
            #pragma unroll
            for (int nj = 0; nj < 8; ++nj) {
                const int cbase = wn * 64 + nj * 8 + 2 * q;
                #pragma unroll
                for (int dp = 0; dp < 2; ++dp) {
                    const int row = wm * 64 + mf * 16 + dp * 8 + (l >> 2);
                    sts_v2f(sb + gaddr(row, cbase), C[mf][nj][2 * dp], C[mf][nj][2 * dp + 1]);
                }
            }
        }
    }
    __syncthreads();

    // ---- epilogue pass 2: coalesced gate fuse + output ----
    {
        const int quad = tid & 15;          // h-quad within CTA (16 quads = 64 h)
        const int r0   = tid >> 4;          // 0..15
        const int h0   = (n0 >> 2) + quad * 4;
        const int cb   = quad * 16;         // gate cols for this quad: [i x4, f x4, o x4, c x4]

        const float4 bi = __ldg((const float4*)(g_bias + n0 + cb));
        const float4 bf = __ldg((const float4*)(g_bias + n0 + cb + 4));
        const float4 bo = __ldg((const float4*)(g_bias + n0 + cb + 8));
        const float4 bc = __ldg((const float4*)(g_bias + n0 + cb + 12));

        #pragma unroll
        for (int p = 0; p < 8; ++p) {
            const int row = r0 + p * 16;
            const long long b = m0 + row;

            float4 gi = lds_v4f(sb + gaddr(row, cb));
            float4 gf = lds_v4f(sb + gaddr(row, cb + 4));
            float4 go = lds_v4f(sb + gaddr(row, cb + 8));
            float4 gc = lds_v4f(sb + gaddr(row, cb + 12));
            float4 co = __ldg((const float4*)(Cold + b * H_ + h0));

            float4 hn, cn;
            {
                float i_ = sig_fast(gi.x + bi.x), f_ = sig_fast(gf.x + bf.x);
                float o_ = sig_fast(go.x + bo.x), ct = tanh_fast(gc.x + bc.x);
                cn.x = fmaf(i_, ct, f_ * co.x);  hn.x = o_ * tanh_fast(cn.x);
            }
            {
                float i_ = sig_fast(gi.y + bi.y), f_ = sig_fast(gf.y + bf.y);
                float o_ = sig_fast(go.y + bo.y), ct = tanh_fast(gc.y + bc.y);
                cn.y = fmaf(i_, ct, f_ * co.y);  hn.y = o_ * tanh_fast(cn.y);
            }
            {
                float i_ = sig_fast(gi.z + bi.z), f_ = sig_fast(gf.z + bf.z);
                float o_ = sig_fast(go.z + bo.z), ct = tanh_fast(gc.z + bc.z);
                cn.z = fmaf(i_, ct, f_ * co.z);  hn.z = o_ * tanh_fast(cn.z);
            }
            {
                float i_ = sig_fast(gi.w + bi.w), f_ = sig_fast(gf.w + bf.w);
                float o_ = sig_fast(go.w + bo.w), ct = tanh_fast(gc.w + bc.w);
                cn.w = fmaf(i_, ct, f_ * co.w);  hn.w = o_ * tanh_fast(cn.w);
            }

            *(float4*)(out + b * H_ + h0)      = hn;
            *(float4*)(out + BH + b * H_ + h0) = cn;
        }
    }
}

// ---------------- harness entry ----------------
extern "C" void kernel_launch(void* const* d_in, const int* in_sizes, int n_in,
                              void* d_out, int out_size) {
    const float* X    = (const float*)d_in[0];  // input_x [B, 256]
    const float* Hold = (const float*)d_in[1];  // h_old   [B, 512]
    const float* Cold = (const float*)d_in[2];  // c_old   [B, 512]
    const float* U    = (const float*)d_in[3];  // [4, 256, 512]
    const float* bU   = (const float*)d_in[4];  // [4, 512]
    const float* W    = (const float*)d_in[5];  // [4, 512, 512]
    const float* bW   = (const float*)d_in[6];  // [4, 512]
    float* out = (float*)d_out;                 // [h_new | c_new]
    (void)in_sizes; (void)n_in; (void)out_size;

    lstm_pack_w<<<(NTOT * KTOT + 255) / 256, 256>>>(U, bU, W, bW);
    lstm_pack_a<<<(B_ * (KTOT / 8) + 255) / 256, 256>>>(X, Hold);

    cudaFuncSetAttribute(lstm_mma_kernel,
                         cudaFuncAttributeMaxDynamicSharedMemorySize, SMEM_BYTES);
    lstm_mma_kernel<<<GM * GN, NTH, SMEM_BYTES>>>(Cold, out);
}

// round 6
// speedup vs baseline: 1.2335x; 1.0342x over previous
#include <cuda_runtime.h>
#include <cuda_fp16.h>
#include <cstdint>

#define DEVINL __device__ __forceinline__

// ---------------- problem constants ----------------
constexpr int B_   = 65536;
constexpr int DIN  = 256;
constexpr int H_   = 512;
constexpr int KTOT = DIN + H_;     // 768
constexpr int NTOT = 4 * H_;       // 2048 packed gate columns
constexpr int BM   = 128;
constexpr int BN   = 256;
constexpr int BKH  = 64;           // k-slice in halves (128 B/row)
constexpr int NIT  = KTOT / BKH;   // 12
constexpr int GN   = NTOT / BN;    // 8
constexpr int GM   = B_ / BM;      // 512
constexpr int NTH  = 256;          // 8 warps: 2 (m) x 4 (n), warp tile 64x64
constexpr long long BH = (long long)B_ * H_;

// smem per stage: A 128x128B = 16K, B 256x128B = 32K
constexpr uint32_t STG_A = 16384;
constexpr uint32_t STG   = 49152;
constexpr int      NSTG  = 4;
constexpr uint32_t SMEM_BYTES = NSTG * STG;   // 196608
// gate buffer (epilogue) reuses bytes [0, 131072) = stages 0..2 (stage 3 still live)

// ---------------- device scratch ----------------
__device__ __half g_Ah[(size_t)B_ * KTOT];   // [b][k] packed [x|h] halves (96 MB)
__device__ __half g_Wth[NTOT * KTOT];        // [n'][k] halves, K contiguous
__device__ float  g_bias[NTOT];

// ---------------- helpers ----------------
DEVINL uint32_t smem_u32(const void* p) {
    uint32_t a;
    asm("{ .reg .u64 t; cvta.to.shared.u64 t, %1; cvt.u32.u64 %0, t; }" : "=r"(a) : "l"(p));
    return a;
}
DEVINL float tanh_fast(float x) { float y; asm("tanh.approx.f32 %0, %1;" : "=f"(y) : "f"(x)); return y; }
DEVINL float sig_fast(float x)  { return fmaf(tanh_fast(0.5f * x), 0.5f, 0.5f); }

DEVINL void ldsm4(uint32_t* r, uint32_t addr) {
    asm volatile("ldmatrix.sync.aligned.m8n8.x4.shared.b16 {%0,%1,%2,%3}, [%4];"
                 : "=r"(r[0]), "=r"(r[1]), "=r"(r[2]), "=r"(r[3]) : "r"(addr));
}
// fp16-accumulate MMA: 2x legacy-pipe rate, one fp16 rounding per K=16 chunk
DEVINL void mma16816h(uint32_t* d, const uint32_t* a, const uint32_t* b) {
    asm volatile("mma.sync.aligned.m16n8k16.row.col.f16.f16.f16.f16 "
                 "{%0,%1}, {%2,%3,%4,%5}, {%6,%7}, {%0,%1};"
                 : "+r"(d[0]), "+r"(d[1])
                 : "r"(a[0]), "r"(a[1]), "r"(a[2]), "r"(a[3]), "r"(b[0]), "r"(b[1]));
}
DEVINL void cpasync16(uint32_t dst, const void* src) {
    asm volatile("cp.async.cg.shared.global [%0], [%1], 16;" :: "r"(dst), "l"(src) : "memory");
}
#define CP_COMMIT() asm volatile("cp.async.commit_group;" ::: "memory")
DEVINL uint32_t h2u(__half2 h) { return *reinterpret_cast<uint32_t*>(&h); }
DEVINL void sts_v2f(uint32_t addr, float a, float b) {
    asm volatile("st.shared.v2.f32 [%0], {%1,%2};" :: "r"(addr), "f"(a), "f"(b) : "memory");
}
DEVINL float4 lds_v4f(uint32_t addr) {
    float4 v;
    asm volatile("ld.shared.v4.f32 {%0,%1,%2,%3}, [%4];"
                 : "=f"(v.x), "=f"(v.y), "=f"(v.z), "=f"(v.w) : "r"(addr));
    return v;
}

// packed column index -> (h, g):  n' = (h>>2)*16 + g*4 + (h&3)
DEVINL void unpack_np(int np, int& h, int& g) {
    int Q = np >> 4, wi = np & 15;
    g = wi >> 2;
    h = (Q << 2) | (wi & 3);
}

// gate-smem swizzled address for (row 0..127, col c 0..255), fp32 elements.
DEVINL uint32_t gaddr(int row, int c) {
    int u = c >> 2;
    int q = u >> 2, j = u & 3;
    int us = (4 * q + (j ^ (q & 3) ^ ((q >> 2) & 3))) ^ (row & 7);
    return (uint32_t)(row * 1024 + us * 16 + (c & 3) * 4);
}

// ---------------- unified pack kernel (one launch -> ncu -s5 hits main) ----------------
constexpr int ACH = B_ * (KTOT / 8);          // A 16B-chunks: 6,291,456
constexpr int WCH = (NTOT * KTOT) / 8;        // W 16B-chunks:   196,608
constexpr int PACK_TOTAL = ACH + WCH + NTOT;  // + bias
__global__ void lstm_pack(const float* __restrict__ U, const float* __restrict__ bU,
                          const float* __restrict__ W, const float* __restrict__ bW,
                          const float* __restrict__ X, const float* __restrict__ Hold) {
    int t = blockIdx.x * 256 + threadIdx.x;
    if (t < ACH) {
        int b  = t / (KTOT / 8);
        int k0 = (t - b * (KTOT / 8)) * 8;
        const float* src = (k0 < DIN) ? (X + (size_t)b * DIN + k0)
                                      : (Hold + (size_t)b * H_ + (k0 - DIN));
        float4 v0 = __ldg((const float4*)src);
        float4 v1 = __ldg((const float4*)(src + 4));
        uint4 o;
        o.x = h2u(__floats2half2_rn(v0.x, v0.y));
        o.y = h2u(__floats2half2_rn(v0.z, v0.w));
        o.z = h2u(__floats2half2_rn(v1.x, v1.y));
        o.w = h2u(__floats2half2_rn(v1.z, v1.w));
        *(uint4*)(g_Ah + (size_t)b * KTOT + k0) = o;
    } else if (t < ACH + WCH) {
        int c0 = (t - ACH) * 8;              // 8 elems, same np row (768 % 8 == 0)
        int np = c0 / KTOT;
        int k0 = c0 - np * KTOT;
        int h, g; unpack_np(np, h, g);
        __half o[8];
        #pragma unroll
        for (int j = 0; j < 8; ++j) {
            int k = k0 + j;
            float v = (k < DIN) ? U[(g * DIN + k) * H_ + h]
                                : W[(g * H_ + (k - DIN)) * H_ + h];
            o[j] = __float2half_rn(v);
        }
        *(uint4*)(g_Wth + c0) = *(const uint4*)o;
    } else if (t < PACK_TOTAL) {
        int np = t - ACH - WCH;
        int h, g; unpack_np(np, h, g);
        g_bias[np] = bU[g * H_ + h] + bW[g * H_ + h];
    }
}

// ---------------- main fused kernel ----------------
__global__ void __launch_bounds__(NTH)
lstm_mma_kernel(const float* __restrict__ Cold, float* __restrict__ out) {
    extern __shared__ char smem[];
    const uint32_t sb = smem_u32(smem);
    const int tid = threadIdx.x;
    const int wid = tid >> 5, l = tid & 31;
    const int s = l & 7;
    const int hi4 = l >> 4;
    const int hi3 = (l >> 3) & 1;

    const int m0 = (int)(blockIdx.x >> 3) * BM;   // n-fastest for A L2 reuse
    const int n0 = (int)(blockIdx.x & 7) * BN;
    const int wm = wid >> 2, wn = wid & 3;        // 2 x 4 warps, each 64(m) x 64(n)

    // ---- ldmatrix row-base addresses ----
    uint32_t a_ld[4], b_ld[4];
    #pragma unroll
    for (int mf = 0; mf < 4; ++mf)
        a_ld[mf] = sb + (uint32_t)((wm * 64 + mf * 16 + (l & 15)) * 128);
    #pragma unroll
    for (int p = 0; p < 4; ++p)
        b_ld[p] = sb + STG_A + (uint32_t)((wn * 64 + p * 16 + hi4 * 8 + (l & 7)) * 128);

    // ---- staging constants ----
    const int ar  = tid >> 1;            // A row 0..127, 2 threads/row
    const int ac0 = (tid & 1) * 4;       // first 16B chunk of 8
    const uint32_t a_dst = sb + (uint32_t)ar * 128u;
    const uint32_t b_dst = sb + STG_A + (uint32_t)tid * 128u;   // B row = tid
    const __half* a_srcb = g_Ah  + (size_t)(m0 + ar)  * KTOT + ac0 * 8;
    const __half* b_srcb = g_Wth + (size_t)(n0 + tid) * KTOT;

    auto stage = [&](int st, int it) {
        const uint32_t so = (uint32_t)st * STG;
        const __half* as = a_srcb + it * BKH;
        #pragma unroll
        for (int j = 0; j < 4; ++j) {
            int c = ac0 + j;
            cpasync16(a_dst + so + (uint32_t)((c ^ (ar & 7)) << 4), as + j * 8);
        }
        const __half* bs = b_srcb + it * BKH;
        #pragma unroll
        for (int j = 0; j < 8; ++j)
            cpasync16(b_dst + so + (uint32_t)((j ^ (tid & 7)) << 4), bs + j * 8);
        CP_COMMIT();
    };

    // ---- accumulators: fp16x2, [mf][nj][row-group] ----
    uint32_t C[4][8][2];
    #pragma unroll
    for (int mf = 0; mf < 4; ++mf)
        #pragma unroll
        for (int nj = 0; nj < 8; ++nj) { C[mf][nj][0] = 0u; C[mf][nj][1] = 0u; }

    auto compute = [&](int st) {
        const uint32_t so = (uint32_t)st * STG;
        #pragma unroll
        for (int kc = 0; kc < 4; ++kc) {
            uint32_t afr[4][4], bfr[4][4];
            const uint32_t aoff = so + (uint32_t)(((2 * kc + hi4) ^ s) << 4);
            const uint32_t boff = so + (uint32_t)(((2 * kc + hi3) ^ s) << 4);
            #pragma unroll
            for (int mf = 0; mf < 4; ++mf) ldsm4(afr[mf], a_ld[mf] + aoff);
            #pragma unroll
            for (int p = 0; p < 4; ++p)    ldsm4(bfr[p], b_ld[p] + boff);
            #pragma unroll
            for (int mf = 0; mf < 4; ++mf)
                #pragma unroll
                for (int nj = 0; nj < 8; ++nj)
                    mma16816h(C[mf][nj], afr[mf], &bfr[nj >> 1][(nj & 1) * 2]);
        }
    };

    // ---- 4-stage pipeline, stage-before-compute, one barrier per iter ----
    stage(0, 0);
    stage(1, 1);
    stage(2, 2);

    for (int it = 0; it < NIT; ++it) {
        if (it < NIT - 2)      asm volatile("cp.async.wait_group 2;" ::: "memory");
        else if (it < NIT - 1) asm volatile("cp.async.wait_group 1;" ::: "memory");
        else                   asm volatile("cp.async.wait_group 0;" ::: "memory");
        __syncthreads();   // (a) tile `it` visible; (b) buf (it+3)%4 fully read
        if (it + 3 < NIT) stage((it + 3) % NSTG, it + 3);
        compute(it % NSTG);
    }

    // ---- epilogue pass 1: frags (half2 -> float2) -> gate smem [0,128K) ----
    // safe without a barrier: last compute reads stage 3 (>= 147456) only.
    {
        const int q = l & 3;
        #pragma unroll
        for (int mf = 0; mf < 4; ++mf) {
            #pragma unroll
            for (int nj = 0; nj < 8; ++nj) {
                const int cbase = wn * 64 + nj * 8 + 2 * q;
                #pragma unroll
                for (int dp = 0; dp < 2; ++dp) {
                    const int row = wm * 64 + mf * 16 + dp * 8 + (l >> 2);
                    float2 v = __half22float2(*reinterpret_cast<const __half2*>(&C[mf][nj][dp]));
                    sts_v2f(sb + gaddr(row, cbase), v.x, v.y);
                }
            }
        }
    }
    __syncthreads();

    // ---- epilogue pass 2: coalesced gate fuse + output ----
    {
        const int quad = tid & 15;          // h-quad within CTA (16 quads = 64 h)
        const int r0   = tid >> 4;          // 0..15
        const int h0   = (n0 >> 2) + quad * 4;
        const int cb   = quad * 16;         // gate cols: [i x4, f x4, o x4, c x4]

        const float4 bi = __ldg((const float4*)(g_bias + n0 + cb));
        const float4 bf = __ldg((const float4*)(g_bias + n0 + cb + 4));
        const float4 bo = __ldg((const float4*)(g_bias + n0 + cb + 8));
        const float4 bc = __ldg((const float4*)(g_bias + n0 + cb + 12));

        #pragma unroll
        for (int p = 0; p < 8; ++p) {
            const int row = r0 + p * 16;
            const long long b = m0 + row;

            float4 gi = lds_v4f(sb + gaddr(row, cb));
            float4 gf = lds_v4f(sb + gaddr(row, cb + 4));
            float4 go = lds_v4f(sb + gaddr(row, cb + 8));
            float4 gc = lds_v4f(sb + gaddr(row, cb + 12));
            float4 co = __ldg((const float4*)(Cold + b * H_ + h0));

            float4 hn, cn;
            {
                float i_ = sig_fast(gi.x + bi.x), f_ = sig_fast(gf.x + bf.x);
                float o_ = sig_fast(go.x + bo.x), ct = tanh_fast(gc.x + bc.x);
                cn.x = fmaf(i_, ct, f_ * co.x);  hn.x = o_ * tanh_fast(cn.x);
            }
            {
                float i_ = sig_fast(gi.y + bi.y), f_ = sig_fast(gf.y + bf.y);
                float o_ = sig_fast(go.y + bo.y), ct = tanh_fast(gc.y + bc.y);
                cn.y = fmaf(i_, ct, f_ * co.y);  hn.y = o_ * tanh_fast(cn.y);
            }
            {
                float i_ = sig_fast(gi.z + bi.z), f_ = sig_fast(gf.z + bf.z);
                float o_ = sig_fast(go.z + bo.z), ct = tanh_fast(gc.z + bc.z);
                cn.z = fmaf(i_, ct, f_ * co.z);  hn.z = o_ * tanh_fast(cn.z);
            }
            {
                float i_ = sig_fast(gi.w + bi.w), f_ = sig_fast(gf.w + bf.w);
                float o_ = sig_fast(go.w + bo.w), ct = tanh_fast(gc.w + bc.w);
                cn.w = fmaf(i_, ct, f_ * co.w);  hn.w = o_ * tanh_fast(cn.w);
            }

            *(float4*)(out + b * H_ + h0)      = hn;
            *(float4*)(out + BH + b * H_ + h0) = cn;
        }
    }
}

// ---------------- harness entry ----------------
extern "C" void kernel_launch(void* const* d_in, const int* in_sizes, int n_in,
                              void* d_out, int out_size) {
    const float* X    = (const float*)d_in[0];  // input_x [B, 256]
    const float* Hold = (const float*)d_in[1];  // h_old   [B, 512]
    const float* Cold = (const float*)d_in[2];  // c_old   [B, 512]
    const float* U    = (const float*)d_in[3];  // [4, 256, 512]
    const float* bU   = (const float*)d_in[4];  // [4, 512]
    const float* W    = (const float*)d_in[5];  // [4, 512, 512]
    const float* bW   = (const float*)d_in[6];  // [4, 512]
    float* out = (float*)d_out;                 // [h_new | c_new]
    (void)in_sizes; (void)n_in; (void)out_size;

    lstm_pack<<<(PACK_TOTAL + 255) / 256, 256>>>(U, bU, W, bW, X, Hold);

    cudaFuncSetAttribute(lstm_mma_kernel,
                         cudaFuncAttributeMaxDynamicSharedMemorySize, SMEM_BYTES);
    lstm_mma_kernel<<<GM * GN, NTH, SMEM_BYTES>>>(Cold, out);
}

// round 7
// speedup vs baseline: 1.5644x; 1.2683x over previous
#include <cuda_runtime.h>
#include <cuda_fp16.h>
#include <cstdint>

#define DEVINL __device__ __forceinline__

// ---------------- problem constants ----------------
constexpr int B_   = 65536;
constexpr int DIN  = 256;
constexpr int H_   = 512;
constexpr int KTOT = DIN + H_;     // 768
constexpr int NTOT = 4 * H_;       // 2048 packed gate columns
constexpr int BM   = 128;
constexpr int BN   = 128;
constexpr int BKH  = 64;           // k-slice in halves (128 B/row)
constexpr int NIT  = KTOT / BKH;   // 12
constexpr int GN   = NTOT / BN;    // 16
constexpr int GM   = B_ / BM;      // 512
constexpr int NTH  = 256;          // 8 warps: 2 (m) x 4 (n), warp tile 64x32
constexpr long long BH = (long long)B_ * H_;

// smem per stage: A 128x128B = 16K, B 128x128B = 16K
constexpr uint32_t STG_A = 16384;
constexpr uint32_t STG   = 32768;
constexpr int      NSTG  = 3;
constexpr uint32_t SMEM_BYTES = NSTG * STG;   // 98304 -> 2 CTAs/SM
// epilogue gate buffer reuses [0, 65536) = stages 0..1 (stage 2 read by last compute)

// ---------------- device scratch ----------------
__device__ __half g_Ah[(size_t)B_ * KTOT];   // [b][k] packed [x|h] halves (96 MB)
__device__ __half g_Wth[NTOT * KTOT];        // [n'][k] halves, K contiguous
__device__ float  g_bias[NTOT];

// ---------------- helpers ----------------
DEVINL uint32_t smem_u32(const void* p) {
    uint32_t a;
    asm("{ .reg .u64 t; cvta.to.shared.u64 t, %1; cvt.u32.u64 %0, t; }" : "=r"(a) : "l"(p));
    return a;
}
DEVINL float tanh_fast(float x) { float y; asm("tanh.approx.f32 %0, %1;" : "=f"(y) : "f"(x)); return y; }
DEVINL float sig_fast(float x)  { return fmaf(tanh_fast(0.5f * x), 0.5f, 0.5f); }

DEVINL void ldsm4(uint32_t* r, uint32_t addr) {
    asm volatile("ldmatrix.sync.aligned.m8n8.x4.shared.b16 {%0,%1,%2,%3}, [%4];"
                 : "=r"(r[0]), "=r"(r[1]), "=r"(r[2]), "=r"(r[3]) : "r"(addr));
}
// fp16-accumulate MMA (2x fp32-accum rate on the legacy pipe)
DEVINL void mma16816h(uint32_t* d, const uint32_t* a, const uint32_t* b) {
    asm volatile("mma.sync.aligned.m16n8k16.row.col.f16.f16.f16.f16 "
                 "{%0,%1}, {%2,%3,%4,%5}, {%6,%7}, {%0,%1};"
                 : "+r"(d[0]), "+r"(d[1])
                 : "r"(a[0]), "r"(a[1]), "r"(a[2]), "r"(a[3]), "r"(b[0]), "r"(b[1]));
}
DEVINL void cpasync16(uint32_t dst, const void* src) {
    asm volatile("cp.async.cg.shared.global [%0], [%1], 16;" :: "r"(dst), "l"(src) : "memory");
}
#define CP_COMMIT() asm volatile("cp.async.commit_group;" ::: "memory")
DEVINL uint32_t h2u(__half2 h) { return *reinterpret_cast<uint32_t*>(&h); }
DEVINL void sts_v2f(uint32_t addr, float a, float b) {
    asm volatile("st.shared.v2.f32 [%0], {%1,%2};" :: "r"(addr), "f"(a), "f"(b) : "memory");
}
DEVINL float4 lds_v4f(uint32_t addr) {
    float4 v;
    asm volatile("ld.shared.v4.f32 {%0,%1,%2,%3}, [%4];"
                 : "=f"(v.x), "=f"(v.y), "=f"(v.z), "=f"(v.w) : "r"(addr));
    return v;
}

// packed column index -> (h, g):  n' = (h>>2)*16 + g*4 + (h&3)
DEVINL void unpack_np(int np, int& h, int& g) {
    int Q = np >> 4, wi = np & 15;
    g = wi >> 2;
    h = (Q << 2) | (wi & 3);
}

// gate-smem swizzled address for (row 0..127, col c 0..127), fp32, 512B row stride.
// 16B unit u = c>>2 (0..31); q = u>>2, j = u&3;
// phys unit = (4q + (j ^ (q&3) ^ ((q>>2)&3))) ^ (row&7)   -- conflict-free for
// pass-1 STS.64 (row varies with l>>2) and pass-2 LDS.128 (q varies with l&7).
DEVINL uint32_t gaddr(int row, int c) {
    int u = c >> 2;
    int q = u >> 2, j = u & 3;
    int us = (4 * q + (j ^ (q & 3) ^ ((q >> 2) & 3))) ^ (row & 7);
    return (uint32_t)(row * 512 + us * 16 + (c & 3) * 4);
}

// ---------------- unified pack kernel ----------------
constexpr int ACH = B_ * (KTOT / 8);          // A 16B-chunks
constexpr int WCH = (NTOT * KTOT) / 8;        // W 16B-chunks
constexpr int PACK_TOTAL = ACH + WCH + NTOT;  // + bias
__global__ void lstm_pack(const float* __restrict__ U, const float* __restrict__ bU,
                          const float* __restrict__ W, const float* __restrict__ bW,
                          const float* __restrict__ X, const float* __restrict__ Hold) {
    int t = blockIdx.x * 256 + threadIdx.x;
    if (t < ACH) {
        int b  = t / (KTOT / 8);
        int k0 = (t - b * (KTOT / 8)) * 8;
        const float* src = (k0 < DIN) ? (X + (size_t)b * DIN + k0)
                                      : (Hold + (size_t)b * H_ + (k0 - DIN));
        float4 v0 = __ldg((const float4*)src);
        float4 v1 = __ldg((const float4*)(src + 4));
        uint4 o;
        o.x = h2u(__floats2half2_rn(v0.x, v0.y));
        o.y = h2u(__floats2half2_rn(v0.z, v0.w));
        o.z = h2u(__floats2half2_rn(v1.x, v1.y));
        o.w = h2u(__floats2half2_rn(v1.z, v1.w));
        *(uint4*)(g_Ah + (size_t)b * KTOT + k0) = o;
    } else if (t < ACH + WCH) {
        int c0 = (t - ACH) * 8;
        int np = c0 / KTOT;
        int k0 = c0 - np * KTOT;
        int h, g; unpack_np(np, h, g);
        __half o[8];
        #pragma unroll
        for (int j = 0; j < 8; ++j) {
            int k = k0 + j;
            float v = (k < DIN) ? U[(g * DIN + k) * H_ + h]
                                : W[(g * H_ + (k - DIN)) * H_ + h];
            o[j] = __float2half_rn(v);
        }
        *(uint4*)(g_Wth + c0) = *(const uint4*)o;
    } else if (t < PACK_TOTAL) {
        int np = t - ACH - WCH;
        int h, g; unpack_np(np, h, g);
        g_bias[np] = bU[g * H_ + h] + bW[g * H_ + h];
    }
}

// ---------------- main fused kernel: 2 CTAs/SM ----------------
__global__ void __launch_bounds__(NTH, 2)
lstm_mma_kernel(const float* __restrict__ Cold, float* __restrict__ out) {
    extern __shared__ char smem[];
    const uint32_t sb = smem_u32(smem);
    const int tid = threadIdx.x;
    const int wid = tid >> 5, l = tid & 31;
    const int s = l & 7;
    const int hi4 = l >> 4;
    const int hi3 = (l >> 3) & 1;

    const int m0 = (int)(blockIdx.x >> 4) * BM;   // n-fastest for A L2 reuse
    const int n0 = (int)(blockIdx.x & 15) * BN;
    const int wm = wid >> 2, wn = wid & 3;        // 2 x 4 warps, each 64(m) x 32(n)

    // ---- ldmatrix row-base addresses ----
    uint32_t a_ld[4], b_ld[2];
    #pragma unroll
    for (int mf = 0; mf < 4; ++mf)
        a_ld[mf] = sb + (uint32_t)((wm * 64 + mf * 16 + (l & 15)) * 128);
    #pragma unroll
    for (int p = 0; p < 2; ++p)
        b_ld[p] = sb + STG_A + (uint32_t)((wn * 32 + p * 16 + hi4 * 8 + (l & 7)) * 128);

    // ---- staging constants: 2 threads per row, 4 x 16B chunks each ----
    const int ar  = tid >> 1;            // row 0..127 (A and B)
    const int ac0 = (tid & 1) * 4;
    const uint32_t a_dst = sb + (uint32_t)ar * 128u;
    const uint32_t b_dst = sb + STG_A + (uint32_t)ar * 128u;
    const __half* a_srcb = g_Ah  + (size_t)(m0 + ar) * KTOT + ac0 * 8;
    const __half* b_srcb = g_Wth + (size_t)(n0 + ar) * KTOT + ac0 * 8;

    auto stage = [&](int st, int it) {
        const uint32_t so = (uint32_t)st * STG;
        const __half* as = a_srcb + it * BKH;
        const __half* bs = b_srcb + it * BKH;
        #pragma unroll
        for (int j = 0; j < 4; ++j) {
            uint32_t off = (uint32_t)(((ac0 + j) ^ (ar & 7)) << 4);
            cpasync16(a_dst + so + off, as + j * 8);
            cpasync16(b_dst + so + off, bs + j * 8);
        }
        CP_COMMIT();
    };

    // ---- accumulators: fp16x2, [mf][nj][row-group] ----
    uint32_t C[4][4][2];
    #pragma unroll
    for (int mf = 0; mf < 4; ++mf)
        #pragma unroll
        for (int nj = 0; nj < 4; ++nj) { C[mf][nj][0] = 0u; C[mf][nj][1] = 0u; }

    auto compute = [&](int st) {
        const uint32_t so = (uint32_t)st * STG;
        #pragma unroll
        for (int kc = 0; kc < 4; ++kc) {
            uint32_t afr[4][4], bfr[2][4];
            const uint32_t aoff = so + (uint32_t)(((2 * kc + hi4) ^ s) << 4);
            const uint32_t boff = so + (uint32_t)(((2 * kc + hi3) ^ s) << 4);
            #pragma unroll
            for (int mf = 0; mf < 4; ++mf) ldsm4(afr[mf], a_ld[mf] + aoff);
            #pragma unroll
            for (int p = 0; p < 2; ++p)    ldsm4(bfr[p], b_ld[p] + boff);
            #pragma unroll
            for (int mf = 0; mf < 4; ++mf)
                #pragma unroll
                for (int nj = 0; nj < 4; ++nj)
                    mma16816h(C[mf][nj], afr[mf], &bfr[nj >> 1][(nj & 1) * 2]);
        }
    };

    // ---- 3-stage pipeline, one barrier per iter ----
    stage(0, 0);
    stage(1, 1);

    for (int it = 0; it < NIT; ++it) {
        if (it < NIT - 1) asm volatile("cp.async.wait_group 1;" ::: "memory");
        else              asm volatile("cp.async.wait_group 0;" ::: "memory");
        __syncthreads();   // (a) tile `it` visible; (b) buf (it+2)%3 fully read
        if (it + 2 < NIT) stage((it + 2) % NSTG, it + 2);
        compute(it % NSTG);
    }

    // ---- epilogue pass 1: frags (half2 -> float2) -> gate smem [0, 64K) ----
    // no barrier needed: last compute reads stage 2 = [65536, 98304) only.
    {
        const int q = l & 3;
        #pragma unroll
        for (int mf = 0; mf < 4; ++mf) {
            #pragma unroll
            for (int nj = 0; nj < 4; ++nj) {
                const int cbase = wn * 32 + nj * 8 + 2 * q;
                #pragma unroll
                for (int dp = 0; dp < 2; ++dp) {
                    const int row = wm * 64 + mf * 16 + dp * 8 + (l >> 2);
                    float2 v = __half22float2(*reinterpret_cast<const __half2*>(&C[mf][nj][dp]));
                    sts_v2f(sb + gaddr(row, cbase), v.x, v.y);
                }
            }
        }
    }
    __syncthreads();

    // ---- epilogue pass 2: coalesced gate fuse + output ----
    {
        const int quad = tid & 7;           // h-quad within CTA (8 quads = 32 h)
        const int r0   = tid >> 3;          // 0..31
        const int h0   = (n0 >> 2) + quad * 4;
        const int cb   = quad * 16;         // gate cols: [i x4, f x4, o x4, c x4]

        const float4 bi = __ldg((const float4*)(g_bias + n0 + cb));
        const float4 bf = __ldg((const float4*)(g_bias + n0 + cb + 4));
        const float4 bo = __ldg((const float4*)(g_bias + n0 + cb + 8));
        const float4 bc = __ldg((const float4*)(g_bias + n0 + cb + 12));

        #pragma unroll
        for (int p = 0; p < 4; ++p) {
            const int row = r0 + p * 32;
            const long long b = m0 + row;

            float4 gi = lds_v4f(sb + gaddr(row, cb));
            float4 gf = lds_v4f(sb + gaddr(row, cb + 4));
            float4 go = lds_v4f(sb + gaddr(row, cb + 8));
            float4 gc = lds_v4f(sb + gaddr(row, cb + 12));
            float4 co = __ldg((const float4*)(Cold + b * H_ + h0));

            float4 hn, cn;
            {
                float i_ = sig_fast(gi.x + bi.x), f_ = sig_fast(gf.x + bf.x);
                float o_ = sig_fast(go.x + bo.x), ct = tanh_fast(gc.x + bc.x);
                cn.x = fmaf(i_, ct, f_ * co.x);  hn.x = o_ * tanh_fast(cn.x);
            }
            {
                float i_ = sig_fast(gi.y + bi.y), f_ = sig_fast(gf.y + bf.y);
                float o_ = sig_fast(go.y + bo.y), ct = tanh_fast(gc.y + bc.y);
                cn.y = fmaf(i_, ct, f_ * co.y);  hn.y = o_ * tanh_fast(cn.y);
            }
            {
                float i_ = sig_fast(gi.z + bi.z), f_ = sig_fast(gf.z + bf.z);
                float o_ = sig_fast(go.z + bo.z), ct = tanh_fast(gc.z + bc.z);
                cn.z = fmaf(i_, ct, f_ * co.z);  hn.z = o_ * tanh_fast(cn.z);
            }
            {
                float i_ = sig_fast(gi.w + bi.w), f_ = sig_fast(gf.w + bf.w);
                float o_ = sig_fast(go.w + bo.w), ct = tanh_fast(gc.w + bc.w);
                cn.w = fmaf(i_, ct, f_ * co.w);  hn.w = o_ * tanh_fast(cn.w);
            }

            *(float4*)(out + b * H_ + h0)      = hn;
            *(float4*)(out + BH + b * H_ + h0) = cn;
        }
    }
}

// ---------------- harness entry ----------------
extern "C" void kernel_launch(void* const* d_in, const int* in_sizes, int n_in,
                              void* d_out, int out_size) {
    const float* X    = (const float*)d_in[0];  // input_x [B, 256]
    const float* Hold = (const float*)d_in[1];  // h_old   [B, 512]
    const float* Cold = (const float*)d_in[2];  // c_old   [B, 512]
    const float* U    = (const float*)d_in[3];  // [4, 256, 512]
    const float* bU   = (const float*)d_in[4];  // [4, 512]
    const float* W    = (const float*)d_in[5];  // [4, 512, 512]
    const float* bW   = (const float*)d_in[6];  // [4, 512]
    float* out = (float*)d_out;                 // [h_new | c_new]
    (void)in_sizes; (void)n_in; (void)out_size;

    lstm_pack<<<(PACK_TOTAL + 255) / 256, 256>>>(U, bU, W, bW, X, Hold);

    cudaFuncSetAttribute(lstm_mma_kernel,
                         cudaFuncAttributeMaxDynamicSharedMemorySize, SMEM_BYTES);
    lstm_mma_kernel<<<GM * GN, NTH, SMEM_BYTES>>>(Cold, out);
}

// round 8
// speedup vs baseline: 1.6721x; 1.0689x over previous
#include <cuda_runtime.h>
#include <cuda_fp16.h>
#include <cstdint>

#define DEVINL __device__ __forceinline__

// ---------------- problem constants ----------------
constexpr int B_   = 65536;
constexpr int DIN  = 256;
constexpr int H_   = 512;
constexpr int KTOT = DIN + H_;     // 768
constexpr int NTOT = 4 * H_;       // 2048 packed gate columns
constexpr int BM   = 128;
constexpr int BN   = 128;
constexpr int BKH  = 64;           // k-slice in halves (128 B/row)
constexpr int NIT  = KTOT / BKH;   // 12
constexpr int GN   = NTOT / BN;    // 16
constexpr int GM   = B_ / BM;      // 512
constexpr int NTH  = 256;          // 8 warps: 2 (m) x 4 (n), warp tile 64x32
constexpr long long BH = (long long)B_ * H_;

// smem per stage: A 128x128B = 16K, B 128x128B = 16K
constexpr uint32_t STG_A = 16384;
constexpr uint32_t STG   = 32768;
constexpr int      NSTG  = 2;
constexpr uint32_t SMEM_BYTES = NSTG * STG;   // 65536 -> 3 CTAs/SM (192 KB)
// epilogue gate half-buffer reuses stage 0 = [0, 32768); last compute reads stage 1.

// ---------------- device scratch ----------------
__device__ __half g_Ah[(size_t)B_ * KTOT];   // [b][k] packed [x|h] halves (96 MB)
__device__ __half g_Wth[NTOT * KTOT];        // [n'][k] halves, K contiguous
__device__ float  g_bias[NTOT];

// ---------------- helpers ----------------
DEVINL uint32_t smem_u32(const void* p) {
    uint32_t a;
    asm("{ .reg .u64 t; cvta.to.shared.u64 t, %1; cvt.u32.u64 %0, t; }" : "=r"(a) : "l"(p));
    return a;
}
DEVINL float tanh_fast(float x) { float y; asm("tanh.approx.f32 %0, %1;" : "=f"(y) : "f"(x)); return y; }
DEVINL float sig_fast(float x)  { return fmaf(tanh_fast(0.5f * x), 0.5f, 0.5f); }

DEVINL void ldsm4(uint32_t* r, uint32_t addr) {
    asm volatile("ldmatrix.sync.aligned.m8n8.x4.shared.b16 {%0,%1,%2,%3}, [%4];"
                 : "=r"(r[0]), "=r"(r[1]), "=r"(r[2]), "=r"(r[3]) : "r"(addr));
}
// fp16-accumulate MMA (2x fp32-accum rate on the legacy pipe)
DEVINL void mma16816h(uint32_t* d, const uint32_t* a, const uint32_t* b) {
    asm volatile("mma.sync.aligned.m16n8k16.row.col.f16.f16.f16.f16 "
                 "{%0,%1}, {%2,%3,%4,%5}, {%6,%7}, {%0,%1};"
                 : "+r"(d[0]), "+r"(d[1])
                 : "r"(a[0]), "r"(a[1]), "r"(a[2]), "r"(a[3]), "r"(b[0]), "r"(b[1]));
}
DEVINL void cpasync16(uint32_t dst, const void* src) {
    asm volatile("cp.async.cg.shared.global [%0], [%1], 16;" :: "r"(dst), "l"(src) : "memory");
}
#define CP_COMMIT() asm volatile("cp.async.commit_group;" ::: "memory")
DEVINL uint32_t h2u(__half2 h) { return *reinterpret_cast<uint32_t*>(&h); }
DEVINL void sts_v2f(uint32_t addr, float a, float b) {
    asm volatile("st.shared.v2.f32 [%0], {%1,%2};" :: "r"(addr), "f"(a), "f"(b) : "memory");
}
DEVINL float4 lds_v4f(uint32_t addr) {
    float4 v;
    asm volatile("ld.shared.v4.f32 {%0,%1,%2,%3}, [%4];"
                 : "=f"(v.x), "=f"(v.y), "=f"(v.z), "=f"(v.w) : "r"(addr));
    return v;
}

// packed column index -> (h, g):  n' = (h>>2)*16 + g*4 + (h&3)
DEVINL void unpack_np(int np, int& h, int& g) {
    int Q = np >> 4, wi = np & 15;
    g = wi >> 2;
    h = (Q << 2) | (wi & 3);
}

// gate-smem swizzled address for (row 0..63 within half, col c 0..127), fp32,
// 512B row stride. Same verified swizzle family as R6/R7.
DEVINL uint32_t gaddr(int row, int c) {
    int u = c >> 2;
    int q = u >> 2, j = u & 3;
    int us = (4 * q + (j ^ (q & 3) ^ ((q >> 2) & 3))) ^ (row & 7);
    return (uint32_t)(row * 512 + us * 16 + (c & 3) * 4);
}

// ---------------- unified pack kernel ----------------
constexpr int ACH = B_ * (KTOT / 8);          // A 16B-chunks
constexpr int WCH = (NTOT * KTOT) / 8;        // W 16B-chunks
constexpr int PACK_TOTAL = ACH + WCH + NTOT;  // + bias
__global__ void lstm_pack(const float* __restrict__ U, const float* __restrict__ bU,
                          const float* __restrict__ W, const float* __restrict__ bW,
                          const float* __restrict__ X, const float* __restrict__ Hold) {
    int t = blockIdx.x * 256 + threadIdx.x;
    if (t < ACH) {
        int b  = t / (KTOT / 8);
        int k0 = (t - b * (KTOT / 8)) * 8;
        const float* src = (k0 < DIN) ? (X + (size_t)b * DIN + k0)
                                      : (Hold + (size_t)b * H_ + (k0 - DIN));
        float4 v0 = __ldg((const float4*)src);
        float4 v1 = __ldg((const float4*)(src + 4));
        uint4 o;
        o.x = h2u(__floats2half2_rn(v0.x, v0.y));
        o.y = h2u(__floats2half2_rn(v0.z, v0.w));
        o.z = h2u(__floats2half2_rn(v1.x, v1.y));
        o.w = h2u(__floats2half2_rn(v1.z, v1.w));
        *(uint4*)(g_Ah + (size_t)b * KTOT + k0) = o;
    } else if (t < ACH + WCH) {
        int c0 = (t - ACH) * 8;
        int np = c0 / KTOT;
        int k0 = c0 - np * KTOT;
        int h, g; unpack_np(np, h, g);
        __half o[8];
        #pragma unroll
        for (int j = 0; j < 8; ++j) {
            int k = k0 + j;
            float v = (k < DIN) ? U[(g * DIN + k) * H_ + h]
                                : W[(g * H_ + (k - DIN)) * H_ + h];
            o[j] = __float2half_rn(v);
        }
        *(uint4*)(g_Wth + c0) = *(const uint4*)o;
    } else if (t < PACK_TOTAL) {
        int np = t - ACH - WCH;
        int h, g; unpack_np(np, h, g);
        g_bias[np] = bU[g * H_ + h] + bW[g * H_ + h];
    }
}

// ---------------- main fused kernel: 3 CTAs/SM ----------------
__global__ void __launch_bounds__(NTH, 3)
lstm_mma_kernel(const float* __restrict__ Cold, float* __restrict__ out) {
    extern __shared__ char smem[];
    const uint32_t sb = smem_u32(smem);
    const int tid = threadIdx.x;
    const int wid = tid >> 5, l = tid & 31;
    const int s = l & 7;
    const int hi4 = l >> 4;
    const int hi3 = (l >> 3) & 1;

    const int m0 = (int)(blockIdx.x >> 4) * BM;   // n-fastest for A L2 reuse
    const int n0 = (int)(blockIdx.x & 15) * BN;
    const int wm = wid >> 2, wn = wid & 3;        // 2 x 4 warps, each 64(m) x 32(n)

    // ---- ldmatrix row-base addresses ----
    uint32_t a_ld[4], b_ld[2];
    #pragma unroll
    for (int mf = 0; mf < 4; ++mf)
        a_ld[mf] = sb + (uint32_t)((wm * 64 + mf * 16 + (l & 15)) * 128);
    #pragma unroll
    for (int p = 0; p < 2; ++p)
        b_ld[p] = sb + STG_A + (uint32_t)((wn * 32 + p * 16 + hi4 * 8 + (l & 7)) * 128);

    // ---- staging constants: 2 threads per row, 4 x 16B chunks each ----
    const int ar  = tid >> 1;            // row 0..127 (A and B)
    const int ac0 = (tid & 1) * 4;
    const uint32_t a_dst = sb + (uint32_t)ar * 128u;
    const uint32_t b_dst = sb + STG_A + (uint32_t)ar * 128u;
    const __half* a_srcb = g_Ah  + (size_t)(m0 + ar) * KTOT + ac0 * 8;
    const __half* b_srcb = g_Wth + (size_t)(n0 + ar) * KTOT + ac0 * 8;

    auto stage = [&](int st, int it) {
        const uint32_t so = (uint32_t)st * STG;
        const __half* as = a_srcb + it * BKH;
        const __half* bs = b_srcb + it * BKH;
        #pragma unroll
        for (int j = 0; j < 4; ++j) {
            uint32_t off = (uint32_t)(((ac0 + j) ^ (ar & 7)) << 4);
            cpasync16(a_dst + so + off, as + j * 8);
            cpasync16(b_dst + so + off, bs + j * 8);
        }
        CP_COMMIT();
    };

    // ---- accumulators: fp16x2, [mf][nj][row-group] ----
    uint32_t C[4][4][2];
    #pragma unroll
    for (int mf = 0; mf < 4; ++mf)
        #pragma unroll
        for (int nj = 0; nj < 4; ++nj) { C[mf][nj][0] = 0u; C[mf][nj][1] = 0u; }

    auto compute = [&](int st) {
        const uint32_t so = (uint32_t)st * STG;
        #pragma unroll
        for (int kc = 0; kc < 4; ++kc) {
            uint32_t afr[4][4], bfr[2][4];
            const uint32_t aoff = so + (uint32_t)(((2 * kc + hi4) ^ s) << 4);
            const uint32_t boff = so + (uint32_t)(((2 * kc + hi3) ^ s) << 4);
            #pragma unroll
            for (int mf = 0; mf < 4; ++mf) ldsm4(afr[mf], a_ld[mf] + aoff);
            #pragma unroll
            for (int p = 0; p < 2; ++p)    ldsm4(bfr[p], b_ld[p] + boff);
            #pragma unroll
            for (int mf = 0; mf < 4; ++mf)
                #pragma unroll
                for (int nj = 0; nj < 4; ++nj)
                    mma16816h(C[mf][nj], afr[mf], &bfr[nj >> 1][(nj & 1) * 2]);
        }
    };

    // ---- 2-stage pipeline: wait -> sync -> prefetch(it+1) -> compute(it) ----
    stage(0, 0);
    for (int it = 0; it < NIT; ++it) {
        asm volatile("cp.async.wait_group 0;" ::: "memory");   // only stage(it) in flight
        __syncthreads();   // (a) tile `it` visible to all; (b) compute(it-1) reads done
        if (it + 1 < NIT) stage((it + 1) & 1, it + 1);
        compute(it & 1);
    }

    // ---- epilogue in two 64-row halves through stage-0 smem (32 KB) ----
    // safe: last compute reads stage 1 = [32768, 65536) only.
    const int q  = l & 3;
    const int quad = tid & 7;           // h-quad within CTA (8 quads = 32 h)
    const int r0   = tid >> 3;          // 0..31
    const int h0   = (n0 >> 2) + quad * 4;
    const int cb   = quad * 16;         // gate cols: [i x4, f x4, o x4, c x4]

    const float4 bi = __ldg((const float4*)(g_bias + n0 + cb));
    const float4 bf = __ldg((const float4*)(g_bias + n0 + cb + 4));
    const float4 bo = __ldg((const float4*)(g_bias + n0 + cb + 8));
    const float4 bc = __ldg((const float4*)(g_bias + n0 + cb + 12));

    #pragma unroll
    for (int hb = 0; hb < 2; ++hb) {
        if (hb == 1) __syncthreads();   // pass-2 reads of half 0 done before overwrite
        // pass 1: warps owning this half dump their frags
        if (wm == hb) {
            #pragma unroll
            for (int mf = 0; mf < 4; ++mf) {
                #pragma unroll
                for (int nj = 0; nj < 4; ++nj) {
                    const int cbase = wn * 32 + nj * 8 + 2 * q;
                    #pragma unroll
                    for (int dp = 0; dp < 2; ++dp) {
                        const int row = mf * 16 + dp * 8 + (l >> 2);   // 0..63 within half
                        float2 v = __half22float2(*reinterpret_cast<const __half2*>(&C[mf][nj][dp]));
                        sts_v2f(sb + gaddr(row, cbase), v.x, v.y);
                    }
                }
            }
        }
        __syncthreads();

        // pass 2: all threads fuse this half's 64 rows (2 rows each)
        #pragma unroll
        for (int p = 0; p < 2; ++p) {
            const int row = r0 + p * 32;                  // 0..63 within half
            const long long b = m0 + hb * 64 + row;

            float4 gi = lds_v4f(sb + gaddr(row, cb));
            float4 gf = lds_v4f(sb + gaddr(row, cb + 4));
            float4 go = lds_v4f(sb + gaddr(row, cb + 8));
            float4 gc = lds_v4f(sb + gaddr(row, cb + 12));
            float4 co = __ldg((const float4*)(Cold + b * H_ + h0));

            float4 hn, cn;
            {
                float i_ = sig_fast(gi.x + bi.x), f_ = sig_fast(gf.x + bf.x);
                float o_ = sig_fast(go.x + bo.x), ct = tanh_fast(gc.x + bc.x);
                cn.x = fmaf(i_, ct, f_ * co.x);  hn.x = o_ * tanh_fast(cn.x);
            }
            {
                float i_ = sig_fast(gi.y + bi.y), f_ = sig_fast(gf.y + bf.y);
                float o_ = sig_fast(go.y + bo.y), ct = tanh_fast(gc.y + bc.y);
                cn.y = fmaf(i_, ct, f_ * co.y);  hn.y = o_ * tanh_fast(cn.y);
            }
            {
                float i_ = sig_fast(gi.z + bi.z), f_ = sig_fast(gf.z + bf.z);
                float o_ = sig_fast(go.z + bo.z), ct = tanh_fast(gc.z + bc.z);
                cn.z = fmaf(i_, ct, f_ * co.z);  hn.z = o_ * tanh_fast(cn.z);
            }
            {
                float i_ = sig_fast(gi.w + bi.w), f_ = sig_fast(gf.w + bf.w);
                float o_ = sig_fast(go.w + bo.w), ct = tanh_fast(gc.w + bc.w);
                cn.w = fmaf(i_, ct, f_ * co.w);  hn.w = o_ * tanh_fast(cn.w);
            }

            *(float4*)(out + b * H_ + h0)      = hn;
            *(float4*)(out + BH + b * H_ + h0) = cn;
        }
    }
}

// ---------------- harness entry ----------------
extern "C" void kernel_launch(void* const* d_in, const int* in_sizes, int n_in,
                              void* d_out, int out_size) {
    const float* X    = (const float*)d_in[0];  // input_x [B, 256]
    const float* Hold = (const float*)d_in[1];  // h_old   [B, 512]
    const float* Cold = (const float*)d_in[2];  // c_old   [B, 512]
    const float* U    = (const float*)d_in[3];  // [4, 256, 512]
    const float* bU   = (const float*)d_in[4];  // [4, 512]
    const float* W    = (const float*)d_in[5];  // [4, 512, 512]
    const float* bW   = (const float*)d_in[6];  // [4, 512]
    float* out = (float*)d_out;                 // [h_new | c_new]
    (void)in_sizes; (void)n_in; (void)out_size;

    lstm_pack<<<(PACK_TOTAL + 255) / 256, 256>>>(U, bU, W, bW, X, Hold);

    cudaFuncSetAttribute(lstm_mma_kernel,
                         cudaFuncAttributeMaxDynamicSharedMemorySize, SMEM_BYTES);
    lstm_mma_kernel<<<GM * GN, NTH, SMEM_BYTES>>>(Cold, out);
}

// round 9
// speedup vs baseline: 1.6830x; 1.0065x over previous
#include <cuda_runtime.h>
#include <cuda_fp16.h>
#include <cstdint>

#define DEVINL __device__ __forceinline__

// ---------------- problem constants ----------------
constexpr int B_   = 65536;
constexpr int DIN  = 256;
constexpr int H_   = 512;
constexpr int KTOT = DIN + H_;     // 768
constexpr int NTOT = 4 * H_;       // 2048 packed gate columns
constexpr int BM   = 128;
constexpr int BN   = 256;
constexpr int BKH  = 64;           // k-slice in halves (128 B/row)
constexpr int NIT  = KTOT / BKH;   // 12
constexpr int GN   = NTOT / BN;    // 8
constexpr int GM   = B_ / BM;      // 512
constexpr int NTH  = 512;          // 16 warps: 2 (m) x 8 (n), warp tile 64x32
constexpr long long BH = (long long)B_ * H_;

// smem per stage: A 128x128B = 16K, B 256x128B = 32K
constexpr uint32_t STG_A = 16384;
constexpr uint32_t STG   = 49152;
constexpr int      NSTG  = 2;
constexpr uint32_t SMEM_BYTES = NSTG * STG;   // 98304 -> 2 CTAs/SM (192 KB)
// epilogue gate quarter-buffer (32 KB) lives in stage 0; last compute reads stage 1.

// ---------------- device scratch ----------------
__device__ __half g_Ah[(size_t)B_ * KTOT];   // [b][k] packed [x|h] halves (96 MB)
__device__ __half g_Wth[NTOT * KTOT];        // [n'][k] halves, K contiguous
__device__ float  g_bias[NTOT];

// ---------------- helpers ----------------
DEVINL uint32_t smem_u32(const void* p) {
    uint32_t a;
    asm("{ .reg .u64 t; cvta.to.shared.u64 t, %1; cvt.u32.u64 %0, t; }" : "=r"(a) : "l"(p));
    return a;
}
DEVINL float tanh_fast(float x) { float y; asm("tanh.approx.f32 %0, %1;" : "=f"(y) : "f"(x)); return y; }
DEVINL float sig_fast(float x)  { return fmaf(tanh_fast(0.5f * x), 0.5f, 0.5f); }

DEVINL void ldsm4(uint32_t* r, uint32_t addr) {
    asm volatile("ldmatrix.sync.aligned.m8n8.x4.shared.b16 {%0,%1,%2,%3}, [%4];"
                 : "=r"(r[0]), "=r"(r[1]), "=r"(r[2]), "=r"(r[3]) : "r"(addr));
}
// fp16-accumulate MMA (2x fp32-accum rate on the legacy pipe)
DEVINL void mma16816h(uint32_t* d, const uint32_t* a, const uint32_t* b) {
    asm volatile("mma.sync.aligned.m16n8k16.row.col.f16.f16.f16.f16 "
                 "{%0,%1}, {%2,%3,%4,%5}, {%6,%7}, {%0,%1};"
                 : "+r"(d[0]), "+r"(d[1])
                 : "r"(a[0]), "r"(a[1]), "r"(a[2]), "r"(a[3]), "r"(b[0]), "r"(b[1]));
}
DEVINL void cpasync16(uint32_t dst, const void* src) {
    asm volatile("cp.async.cg.shared.global [%0], [%1], 16;" :: "r"(dst), "l"(src) : "memory");
}
#define CP_COMMIT() asm volatile("cp.async.commit_group;" ::: "memory")
DEVINL uint32_t h2u(__half2 h) { return *reinterpret_cast<uint32_t*>(&h); }
DEVINL void sts_v2f(uint32_t addr, float a, float b) {
    asm volatile("st.shared.v2.f32 [%0], {%1,%2};" :: "r"(addr), "f"(a), "f"(b) : "memory");
}
DEVINL float4 lds_v4f(uint32_t addr) {
    float4 v;
    asm volatile("ld.shared.v4.f32 {%0,%1,%2,%3}, [%4];"
                 : "=f"(v.x), "=f"(v.y), "=f"(v.z), "=f"(v.w) : "r"(addr));
    return v;
}

// packed column index -> (h, g):  n' = (h>>2)*16 + g*4 + (h&3)
DEVINL void unpack_np(int np, int& h, int& g) {
    int Q = np >> 4, wi = np & 15;
    g = wi >> 2;
    h = (Q << 2) | (wi & 3);
}

// gate-smem swizzled address, quarter buffer: (row 0..31, col c 0..255), fp32,
// 1024B row stride. u = c>>2 (0..63), q = u>>2 (0..15), j = u&3.
// phys unit = (4q + (j ^ (q&3) ^ ((q>>2)&3))) ^ (row&7): conflict-free for
// pass-1 STS.64 (rows vary) and pass-2 LDS.128 (q varies across lanes).
DEVINL uint32_t gaddr(int row, int c) {
    int u = c >> 2;
    int q = u >> 2, j = u & 3;
    int us = (4 * q + (j ^ (q & 3) ^ ((q >> 2) & 3))) ^ (row & 7);
    return (uint32_t)(row * 1024 + us * 16 + (c & 3) * 4);
}

// ---------------- unified pack kernel ----------------
constexpr int ACH = B_ * (KTOT / 8);          // A 16B-chunks
constexpr int WCH = (NTOT * KTOT) / 8;        // W 16B-chunks
constexpr int PACK_TOTAL = ACH + WCH + NTOT;  // + bias
__global__ void lstm_pack(const float* __restrict__ U, const float* __restrict__ bU,
                          const float* __restrict__ W, const float* __restrict__ bW,
                          const float* __restrict__ X, const float* __restrict__ Hold) {
    int t = blockIdx.x * 256 + threadIdx.x;
    if (t < ACH) {
        int b  = t / (KTOT / 8);
        int k0 = (t - b * (KTOT / 8)) * 8;
        const float* src = (k0 < DIN) ? (X + (size_t)b * DIN + k0)
                                      : (Hold + (size_t)b * H_ + (k0 - DIN));
        float4 v0 = __ldg((const float4*)src);
        float4 v1 = __ldg((const float4*)(src + 4));
        uint4 o;
        o.x = h2u(__floats2half2_rn(v0.x, v0.y));
        o.y = h2u(__floats2half2_rn(v0.z, v0.w));
        o.z = h2u(__floats2half2_rn(v1.x, v1.y));
        o.w = h2u(__floats2half2_rn(v1.z, v1.w));
        *(uint4*)(g_Ah + (size_t)b * KTOT + k0) = o;
    } else if (t < ACH + WCH) {
        int c0 = (t - ACH) * 8;
        int np = c0 / KTOT;
        int k0 = c0 - np * KTOT;
        int h, g; unpack_np(np, h, g);
        __half o[8];
        #pragma unroll
        for (int j = 0; j < 8; ++j) {
            int k = k0 + j;
            float v = (k < DIN) ? U[(g * DIN + k) * H_ + h]
                                : W[(g * H_ + (k - DIN)) * H_ + h];
            o[j] = __float2half_rn(v);
        }
        *(uint4*)(g_Wth + c0) = *(const uint4*)o;
    } else if (t < PACK_TOTAL) {
        int np = t - ACH - WCH;
        int h, g; unpack_np(np, h, g);
        g_bias[np] = bU[g * H_ + h] + bW[g * H_ + h];
    }
}

// ---------------- main fused kernel: 512 threads, 2 CTAs/SM (32 warps) ----------------
__global__ void __launch_bounds__(NTH, 2)
lstm_mma_kernel(const float* __restrict__ Cold, float* __restrict__ out) {
    extern __shared__ char smem[];
    const uint32_t sb = smem_u32(smem);
    const int tid = threadIdx.x;
    const int wid = tid >> 5, l = tid & 31;
    const int s = l & 7;
    const int hi4 = l >> 4;
    const int hi3 = (l >> 3) & 1;

    const int m0 = (int)(blockIdx.x >> 3) * BM;   // n-fastest for A L2 reuse
    const int n0 = (int)(blockIdx.x & 7) * BN;
    const int wm = wid >> 3, wn = wid & 7;        // 2 x 8 warps, each 64(m) x 32(n)

    // ---- ldmatrix row-base addresses (stage offset added per use) ----
    uint32_t a_ld[4], b_ld[2];
    #pragma unroll
    for (int mf = 0; mf < 4; ++mf)
        a_ld[mf] = sb + (uint32_t)((wm * 64 + mf * 16 + (l & 15)) * 128);
    #pragma unroll
    for (int p = 0; p < 2; ++p)
        b_ld[p] = sb + STG_A + (uint32_t)((wn * 32 + p * 16 + hi4 * 8 + (l & 7)) * 128);

    // ---- staging constants (512 threads) ----
    const int ar  = tid >> 2;            // A row 0..127, 4 threads/row
    const int ac0 = (tid & 3) * 2;       // 2 chunks of 16B each
    const int br  = tid >> 1;            // B row 0..255, 2 threads/row
    const int bc0 = (tid & 1) * 4;       // 4 chunks of 16B each
    const uint32_t a_dst = sb + (uint32_t)ar * 128u;
    const uint32_t b_dst = sb + STG_A + (uint32_t)br * 128u;
    const __half* a_srcb = g_Ah  + (size_t)(m0 + ar) * KTOT + ac0 * 8;
    const __half* b_srcb = g_Wth + (size_t)(n0 + br) * KTOT + bc0 * 8;

    auto stage = [&](int st, int it) {
        const uint32_t so = (uint32_t)st * STG;
        const __half* as = a_srcb + it * BKH;
        const __half* bs = b_srcb + it * BKH;
        #pragma unroll
        for (int j = 0; j < 2; ++j)
            cpasync16(a_dst + so + (uint32_t)(((ac0 + j) ^ (ar & 7)) << 4), as + j * 8);
        #pragma unroll
        for (int j = 0; j < 4; ++j)
            cpasync16(b_dst + so + (uint32_t)(((bc0 + j) ^ (br & 7)) << 4), bs + j * 8);
        CP_COMMIT();
    };

    // ---- accumulators: fp16x2, [mf][nj][row-group] ----
    uint32_t C[4][4][2];
    #pragma unroll
    for (int mf = 0; mf < 4; ++mf)
        #pragma unroll
        for (int nj = 0; nj < 4; ++nj) { C[mf][nj][0] = 0u; C[mf][nj][1] = 0u; }

    auto compute = [&](int st) {
        const uint32_t so = (uint32_t)st * STG;
        #pragma unroll
        for (int kc = 0; kc < 4; ++kc) {
            uint32_t afr[4][4], bfr[2][4];
            const uint32_t aoff = so + (uint32_t)(((2 * kc + hi4) ^ s) << 4);
            const uint32_t boff = so + (uint32_t)(((2 * kc + hi3) ^ s) << 4);
            #pragma unroll
            for (int mf = 0; mf < 4; ++mf) ldsm4(afr[mf], a_ld[mf] + aoff);
            #pragma unroll
            for (int p = 0; p < 2; ++p)    ldsm4(bfr[p], b_ld[p] + boff);
            #pragma unroll
            for (int mf = 0; mf < 4; ++mf)
                #pragma unroll
                for (int nj = 0; nj < 4; ++nj)
                    mma16816h(C[mf][nj], afr[mf], &bfr[nj >> 1][(nj & 1) * 2]);
        }
    };

    // ---- 2-stage pipeline: wait -> sync -> prefetch(it+1) -> compute(it) ----
    stage(0, 0);
    for (int it = 0; it < NIT; ++it) {
        asm volatile("cp.async.wait_group 0;" ::: "memory");
        __syncthreads();   // (a) tile `it` visible; (b) compute(it-1) reads done
        if (it + 1 < NIT) stage((it + 1) & 1, it + 1);
        compute(it & 1);
    }

    // ---- epilogue: four 32-row quarters through stage-0 smem (32 KB) ----
    // safe: last compute (it=11) reads stage 1 = [49152, 98304) only.
    const int q    = l & 3;
    const int quad = tid & 15;          // h-quad within CTA (16 quads = 64 h)
    const int r0   = tid >> 4;          // 0..31
    const int h0   = (n0 >> 2) + quad * 4;
    const int cb   = quad * 16;         // gate cols: [i x4, f x4, o x4, c x4]

    const float4 bi = __ldg((const float4*)(g_bias + n0 + cb));
    const float4 bf = __ldg((const float4*)(g_bias + n0 + cb + 4));
    const float4 bo = __ldg((const float4*)(g_bias + n0 + cb + 8));
    const float4 bc = __ldg((const float4*)(g_bias + n0 + cb + 12));

    #pragma unroll
    for (int qtr = 0; qtr < 4; ++qtr) {
        if (qtr) __syncthreads();       // previous quarter's pass-2 reads done
        // pass 1: owner warps dump their 2 mf-frag rows for this quarter
        if (wm == (qtr >> 1)) {
            #pragma unroll
            for (int mfl = 0; mfl < 2; ++mfl) {
                const int mf = 2 * (qtr & 1) + mfl;
                #pragma unroll
                for (int nj = 0; nj < 4; ++nj) {
                    const int cbase = wn * 32 + nj * 8 + 2 * q;
                    #pragma unroll
                    for (int dp = 0; dp < 2; ++dp) {
                        const int row = mfl * 16 + dp * 8 + (l >> 2);   // 0..31
                        float2 v = __half22float2(*reinterpret_cast<const __half2*>(&C[mf][nj][dp]));
                        sts_v2f(sb + gaddr(row, cbase), v.x, v.y);
                    }
                }
            }
        }
        __syncthreads();

        // pass 2: 512 threads fuse 32 rows x 64 h (one (row, h-quad) each)
        {
            const long long b = m0 + qtr * 32 + r0;

            float4 gi = lds_v4f(sb + gaddr(r0, cb));
            float4 gf = lds_v4f(sb + gaddr(r0, cb + 4));
            float4 go = lds_v4f(sb + gaddr(r0, cb + 8));
            float4 gc = lds_v4f(sb + gaddr(r0, cb + 12));
            float4 co = __ldg((const float4*)(Cold + b * H_ + h0));

            float4 hn, cn;
            {
                float i_ = sig_fast(gi.x + bi.x), f_ = sig_fast(gf.x + bf.x);
                float o_ = sig_fast(go.x + bo.x), ct = tanh_fast(gc.x + bc.x);
                cn.x = fmaf(i_, ct, f_ * co.x);  hn.x = o_ * tanh_fast(cn.x);
            }
            {
                float i_ = sig_fast(gi.y + bi.y), f_ = sig_fast(gf.y + bf.y);
                float o_ = sig_fast(go.y + bo.y), ct = tanh_fast(gc.y + bc.y);
                cn.y = fmaf(i_, ct, f_ * co.y);  hn.y = o_ * tanh_fast(cn.y);
            }
            {
                float i_ = sig_fast(gi.z + bi.z), f_ = sig_fast(gf.z + bf.z);
                float o_ = sig_fast(go.z + bo.z), ct = tanh_fast(gc.z + bc.z);
                cn.z = fmaf(i_, ct, f_ * co.z);  hn.z = o_ * tanh_fast(cn.z);
            }
            {
                float i_ = sig_fast(gi.w + bi.w), f_ = sig_fast(gf.w + bf.w);
                float o_ = sig_fast(go.w + bo.w), ct = tanh_fast(gc.w + bc.w);
                cn.w = fmaf(i_, ct, f_ * co.w);  hn.w = o_ * tanh_fast(cn.w);
            }

            *(float4*)(out + b * H_ + h0)      = hn;
            *(float4*)(out + BH + b * H_ + h0) = cn;
        }
    }
}

// ---------------- harness entry ----------------
extern "C" void kernel_launch(void* const* d_in, const int* in_sizes, int n_in,
                              void* d_out, int out_size) {
    const float* X    = (const float*)d_in[0];  // input_x [B, 256]
    const float* Hold = (const float*)d_in[1];  // h_old   [B, 512]
    const float* Cold = (const float*)d_in[2];  // c_old   [B, 512]
    const float* U    = (const float*)d_in[3];  // [4, 256, 512]
    const float* bU   = (const float*)d_in[4];  // [4, 512]
    const float* W    = (const float*)d_in[5];  // [4, 512, 512]
    const float* bW   = (const float*)d_in[6];  // [4, 512]
    float* out = (float*)d_out;                 // [h_new | c_new]
    (void)in_sizes; (void)n_in; (void)out_size;

    lstm_pack<<<(PACK_TOTAL + 255) / 256, 256>>>(U, bU, W, bW, X, Hold);

    cudaFuncSetAttribute(lstm_mma_kernel,
                         cudaFuncAttributeMaxDynamicSharedMemorySize, SMEM_BYTES);
    lstm_mma_kernel<<<GM * GN, NTH, SMEM_BYTES>>>(Cold, out);
}

// round 10
// speedup vs baseline: 1.9115x; 1.1358x over previous
#include <cuda_runtime.h>
#include <cuda_fp16.h>
#include <cstdint>

#define DEVINL __device__ __forceinline__

// ---------------- problem constants ----------------
constexpr int B_   = 65536;
constexpr int DIN  = 256;
constexpr int H_   = 512;
constexpr int KTOT = DIN + H_;     // 768
constexpr int NTOT = 4 * H_;       // 2048 packed gate columns
constexpr int BM   = 128;
constexpr int BN   = 256;
constexpr int BKH  = 64;           // k-slice in halves (128 B/row)
constexpr int NIT  = KTOT / BKH;   // 12
constexpr int GN   = NTOT / BN;    // 8
constexpr int GM   = B_ / BM;      // 512
constexpr int NTH  = 512;          // 16 warps: 2 (m) x 8 (n), warp tile 64x32
constexpr long long BH = (long long)B_ * H_;

// smem per stage: A 128x128B = 16K, B 256x128B = 32K
constexpr uint32_t STG_A = 16384;
constexpr uint32_t STG   = 49152;
constexpr uint32_t SMEM_BYTES = 2 * STG;      // 98304 -> 2 CTAs/SM (192 KB)
// epilogue gate quarter-buffer (32 KB) lives in stage 0; last compute reads stage 1.

// ---------------- device scratch ----------------
__device__ __half g_Ah[(size_t)B_ * KTOT];   // [b][k] packed [x|h] halves (96 MB)
__device__ __half g_Wth[NTOT * KTOT];        // [n'][k] halves, K contiguous
__device__ float  g_bias[NTOT];

// ---------------- helpers ----------------
DEVINL uint32_t smem_u32(const void* p) {
    uint32_t a;
    asm("{ .reg .u64 t; cvta.to.shared.u64 t, %1; cvt.u32.u64 %0, t; }" : "=r"(a) : "l"(p));
    return a;
}
DEVINL float tanh_fast(float x) { float y; asm("tanh.approx.f32 %0, %1;" : "=f"(y) : "f"(x)); return y; }
DEVINL float sig_fast(float x)  { return fmaf(tanh_fast(0.5f * x), 0.5f, 0.5f); }

DEVINL void ldsm4(uint32_t* r, uint32_t addr) {
    asm volatile("ldmatrix.sync.aligned.m8n8.x4.shared.b16 {%0,%1,%2,%3}, [%4];"
                 : "=r"(r[0]), "=r"(r[1]), "=r"(r[2]), "=r"(r[3]) : "r"(addr));
}
// fp16-accumulate MMA (2x fp32-accum rate on the legacy pipe)
DEVINL void mma16816h(uint32_t* d, const uint32_t* a, const uint32_t* b) {
    asm volatile("mma.sync.aligned.m16n8k16.row.col.f16.f16.f16.f16 "
                 "{%0,%1}, {%2,%3,%4,%5}, {%6,%7}, {%0,%1};"
                 : "+r"(d[0]), "+r"(d[1])
                 : "r"(a[0]), "r"(a[1]), "r"(a[2]), "r"(a[3]), "r"(b[0]), "r"(b[1]));
}
DEVINL void cpasync16(uint32_t dst, const void* src) {
    asm volatile("cp.async.cg.shared.global [%0], [%1], 16;" :: "r"(dst), "l"(src) : "memory");
}
#define CP_COMMIT() asm volatile("cp.async.commit_group;" ::: "memory")
DEVINL uint32_t h2u(__half2 h) { return *reinterpret_cast<uint32_t*>(&h); }
DEVINL void sts_v2f(uint32_t addr, float a, float b) {
    asm volatile("st.shared.v2.f32 [%0], {%1,%2};" :: "r"(addr), "f"(a), "f"(b) : "memory");
}
DEVINL float4 lds_v4f(uint32_t addr) {
    float4 v;
    asm volatile("ld.shared.v4.f32 {%0,%1,%2,%3}, [%4];"
                 : "=f"(v.x), "=f"(v.y), "=f"(v.z), "=f"(v.w) : "r"(addr));
    return v;
}

// packed column index -> (h, g):  n' = (h>>2)*16 + g*4 + (h&3)
DEVINL void unpack_np(int np, int& h, int& g) {
    int Q = np >> 4, wi = np & 15;
    g = wi >> 2;
    h = (Q << 2) | (wi & 3);
}

// gate-smem swizzled address, quarter buffer: (row 0..31, col c 0..255), fp32,
// 1024B row stride. Conflict-free for pass-1 STS.64 and pass-2 LDS.128.
DEVINL uint32_t gaddr(int row, int c) {
    int u = c >> 2;
    int q = u >> 2, j = u & 3;
    int us = (4 * q + (j ^ (q & 3) ^ ((q >> 2) & 3))) ^ (row & 7);
    return (uint32_t)(row * 1024 + us * 16 + (c & 3) * 4);
}

// ---------------- unified pack kernel ----------------
constexpr int ACH = B_ * (KTOT / 8);          // A 16B-chunks
constexpr int WCH = (NTOT * KTOT) / 8;        // W 16B-chunks
constexpr int PACK_TOTAL = ACH + WCH + NTOT;  // + bias
__global__ void lstm_pack(const float* __restrict__ U, const float* __restrict__ bU,
                          const float* __restrict__ W, const float* __restrict__ bW,
                          const float* __restrict__ X, const float* __restrict__ Hold) {
    int t = blockIdx.x * 256 + threadIdx.x;
    if (t < ACH) {
        int b  = t / (KTOT / 8);
        int k0 = (t - b * (KTOT / 8)) * 8;
        const float* src = (k0 < DIN) ? (X + (size_t)b * DIN + k0)
                                      : (Hold + (size_t)b * H_ + (k0 - DIN));
        float4 v0 = __ldg((const float4*)src);
        float4 v1 = __ldg((const float4*)(src + 4));
        uint4 o;
        o.x = h2u(__floats2half2_rn(v0.x, v0.y));
        o.y = h2u(__floats2half2_rn(v0.z, v0.w));
        o.z = h2u(__floats2half2_rn(v1.x, v1.y));
        o.w = h2u(__floats2half2_rn(v1.z, v1.w));
        *(uint4*)(g_Ah + (size_t)b * KTOT + k0) = o;
    } else if (t < ACH + WCH) {
        int c0 = (t - ACH) * 8;
        int np = c0 / KTOT;
        int k0 = c0 - np * KTOT;
        int h, g; unpack_np(np, h, g);
        __half o[8];
        #pragma unroll
        for (int j = 0; j < 8; ++j) {
            int k = k0 + j;
            float v = (k < DIN) ? U[(g * DIN + k) * H_ + h]
                                : W[(g * H_ + (k - DIN)) * H_ + h];
            o[j] = __float2half_rn(v);
        }
        *(uint4*)(g_Wth + c0) = *(const uint4*)o;
    } else if (t < PACK_TOTAL) {
        int np = t - ACH - WCH;
        int h, g; unpack_np(np, h, g);
        g_bias[np] = bU[g * H_ + h] + bW[g * H_ + h];
    }
}

// ---------------- main fused kernel: 512 threads, 2 CTAs/SM ----------------
__global__ void __launch_bounds__(NTH, 2)
lstm_mma_kernel(const float* __restrict__ Cold, float* __restrict__ out) {
    extern __shared__ char smem[];
    const uint32_t sb = smem_u32(smem);
    const int tid = threadIdx.x;
    const int wid = tid >> 5, l = tid & 31;
    const int s = l & 7;
    const int hi4 = l >> 4;
    const int hi3 = (l >> 3) & 1;

    const int m0 = (int)(blockIdx.x >> 3) * BM;   // n-fastest for A L2 reuse
    const int n0 = (int)(blockIdx.x & 7) * BN;
    const int wm = wid >> 3, wn = wid & 7;        // 2 x 8 warps, each 64(m) x 32(n)

    // ---- ldmatrix row-base addresses + precomputed per-kc offsets ----
    uint32_t a_ld[4], b_ld[2], aoffs[4], boffs[4];
    #pragma unroll
    for (int mf = 0; mf < 4; ++mf)
        a_ld[mf] = sb + (uint32_t)((wm * 64 + mf * 16 + (l & 15)) * 128);
    #pragma unroll
    for (int p = 0; p < 2; ++p)
        b_ld[p] = sb + STG_A + (uint32_t)((wn * 32 + p * 16 + hi4 * 8 + (l & 7)) * 128);
    #pragma unroll
    for (int kc = 0; kc < 4; ++kc) {
        aoffs[kc] = (uint32_t)(((2 * kc + hi4) ^ s) << 4);
        boffs[kc] = (uint32_t)(((2 * kc + hi3) ^ s) << 4);
    }

    // ---- staging constants (512 threads) ----
    const int ar  = tid >> 2;            // A row 0..127, 4 threads/row
    const int ac0 = (tid & 3) * 2;       // 2 chunks of 16B each
    const int br  = tid >> 1;            // B row 0..255, 2 threads/row
    const int bc0 = (tid & 1) * 4;       // 4 chunks of 16B each
    uint32_t a_sdst[2], b_sdst[4];
    #pragma unroll
    for (int j = 0; j < 2; ++j)
        a_sdst[j] = sb + (uint32_t)ar * 128u + (uint32_t)(((ac0 + j) ^ (ar & 7)) << 4);
    #pragma unroll
    for (int j = 0; j < 4; ++j)
        b_sdst[j] = sb + STG_A + (uint32_t)br * 128u + (uint32_t)(((bc0 + j) ^ (br & 7)) << 4);
    const __half* a_srcb = g_Ah  + (size_t)(m0 + ar) * KTOT + ac0 * 8;
    const __half* b_srcb = g_Wth + (size_t)(n0 + br) * KTOT + bc0 * 8;

    auto stage = [&](uint32_t so, int it) {
        const __half* as = a_srcb + it * BKH;   // constant-folds under full unroll
        const __half* bs = b_srcb + it * BKH;
        #pragma unroll
        for (int j = 0; j < 2; ++j) cpasync16(a_sdst[j] + so, as + j * 8);
        #pragma unroll
        for (int j = 0; j < 4; ++j) cpasync16(b_sdst[j] + so, bs + j * 8);
        CP_COMMIT();
    };

    // ---- accumulators: fp16x2, [mf][nj][row-group] ----
    uint32_t C[4][4][2];
    #pragma unroll
    for (int mf = 0; mf < 4; ++mf)
        #pragma unroll
        for (int nj = 0; nj < 4; ++nj) { C[mf][nj][0] = 0u; C[mf][nj][1] = 0u; }

    auto compute = [&](uint32_t so) {
        #pragma unroll
        for (int kc = 0; kc < 4; ++kc) {
            uint32_t afr[4][4], bfr[2][4];
            #pragma unroll
            for (int mf = 0; mf < 4; ++mf) ldsm4(afr[mf], a_ld[mf] + so + aoffs[kc]);
            #pragma unroll
            for (int p = 0; p < 2; ++p)    ldsm4(bfr[p], b_ld[p] + so + boffs[kc]);
            #pragma unroll
            for (int mf = 0; mf < 4; ++mf)
                #pragma unroll
                for (int nj = 0; nj < 4; ++nj)
                    mma16816h(C[mf][nj], afr[mf], &bfr[nj >> 1][(nj & 1) * 2]);
        }
    };

    // ---- fully-unrolled 2-stage pipeline: constants fold into [R+imm] forms ----
    stage(0, 0);
    #pragma unroll
    for (int it = 0; it < NIT; ++it) {
        asm volatile("cp.async.wait_group 0;" ::: "memory");
        __syncthreads();   // (a) tile `it` visible; (b) compute(it-1) reads done
        if (it + 1 < NIT) stage(((it + 1) & 1) ? STG : 0u, it + 1);
        compute((it & 1) ? STG : 0u);
    }

    // ---- epilogue: four 32-row quarters through stage-0 smem (32 KB) ----
    // safe: last compute (it=11) reads stage 1 = [49152, 98304) only.
    const int q    = l & 3;
    const int quad = tid & 15;          // h-quad within CTA (16 quads = 64 h)
    const int r0   = tid >> 4;          // 0..31
    const int h0   = (n0 >> 2) + quad * 4;
    const int cb   = quad * 16;         // gate cols: [i x4, f x4, o x4, c x4]

    const float4 bi = __ldg((const float4*)(g_bias + n0 + cb));
    const float4 bf = __ldg((const float4*)(g_bias + n0 + cb + 4));
    const float4 bo = __ldg((const float4*)(g_bias + n0 + cb + 8));
    const float4 bc = __ldg((const float4*)(g_bias + n0 + cb + 12));

    #pragma unroll
    for (int qtr = 0; qtr < 4; ++qtr) {
        if (qtr) __syncthreads();       // previous quarter's pass-2 reads done
        // pass 1: owner warps dump their 2 mf-frag rows for this quarter
        if (wm == (qtr >> 1)) {
            #pragma unroll
            for (int mfl = 0; mfl < 2; ++mfl) {
                const int mf = 2 * (qtr & 1) + mfl;
                #pragma unroll
                for (int nj = 0; nj < 4; ++nj) {
                    const int cbase = wn * 32 + nj * 8 + 2 * q;
                    #pragma unroll
                    for (int dp = 0; dp < 2; ++dp) {
                        const int row = mfl * 16 + dp * 8 + (l >> 2);   // 0..31
                        float2 v = __half22float2(*reinterpret_cast<const __half2*>(&C[mf][nj][dp]));
                        sts_v2f(sb + gaddr(row, cbase), v.x, v.y);
                    }
                }
            }
        }
        __syncthreads();

        // pass 2: 512 threads fuse 32 rows x 64 h (one (row, h-quad) each)
        {
            const long long b = m0 + qtr * 32 + r0;

            float4 gi = lds_v4f(sb + gaddr(r0, cb));
            float4 gf = lds_v4f(sb + gaddr(r0, cb + 4));
            float4 go = lds_v4f(sb + gaddr(r0, cb + 8));
            float4 gc = lds_v4f(sb + gaddr(r0, cb + 12));
            float4 co = __ldg((const float4*)(Cold + b * H_ + h0));

            float4 hn, cn;
            {
                float i_ = sig_fast(gi.x + bi.x), f_ = sig_fast(gf.x + bf.x);
                float o_ = sig_fast(go.x + bo.x), ct = tanh_fast(gc.x + bc.x);
                cn.x = fmaf(i_, ct, f_ * co.x);  hn.x = o_ * tanh_fast(cn.x);
            }
            {
                float i_ = sig_fast(gi.y + bi.y), f_ = sig_fast(gf.y + bf.y);
                float o_ = sig_fast(go.y + bo.y), ct = tanh_fast(gc.y + bc.y);
                cn.y = fmaf(i_, ct, f_ * co.y);  hn.y = o_ * tanh_fast(cn.y);
            }
            {
                float i_ = sig_fast(gi.z + bi.z), f_ = sig_fast(gf.z + bf.z);
                float o_ = sig_fast(go.z + bo.z), ct = tanh_fast(gc.z + bc.z);
                cn.z = fmaf(i_, ct, f_ * co.z);  hn.z = o_ * tanh_fast(cn.z);
            }
            {
                float i_ = sig_fast(gi.w + bi.w), f_ = sig_fast(gf.w + bf.w);
                float o_ = sig_fast(go.w + bo.w), ct = tanh_fast(gc.w + bc.w);
                cn.w = fmaf(i_, ct, f_ * co.w);  hn.w = o_ * tanh_fast(cn.w);
            }

            *(float4*)(out + b * H_ + h0)      = hn;
            *(float4*)(out + BH + b * H_ + h0) = cn;
        }
    }
}

// ---------------- harness entry ----------------
extern "C" void kernel_launch(void* const* d_in, const int* in_sizes, int n_in,
                              void* d_out, int out_size) {
    const float* X    = (const float*)d_in[0];  // input_x [B, 256]
    const float* Hold = (const float*)d_in[1];  // h_old   [B, 512]
    const float* Cold = (const float*)d_in[2];  // c_old   [B, 512]
    const float* U    = (const float*)d_in[3];  // [4, 256, 512]
    const float* bU   = (const float*)d_in[4];  // [4, 512]
    const float* W    = (const float*)d_in[5];  // [4, 512, 512]
    const float* bW   = (const float*)d_in[6];  // [4, 512]
    float* out = (float*)d_out;                 // [h_new | c_new]
    (void)in_sizes; (void)n_in; (void)out_size;

    lstm_pack<<<(PACK_TOTAL + 255) / 256, 256>>>(U, bU, W, bW, X, Hold);

    cudaFuncSetAttribute(lstm_mma_kernel,
                         cudaFuncAttributeMaxDynamicSharedMemorySize, SMEM_BYTES);
    lstm_mma_kernel<<<GM * GN, NTH, SMEM_BYTES>>>(Cold, out);
}